// round 13
// baseline (speedup 1.0000x reference)
#include <cuda_runtime.h>
#include <cuda_fp16.h>
#include <cstdint>
#include <cstddef>

// ---------------------------------------------------------------------------
// OCR head on GB300 — Round 13: R10 schedule (774.6us best) + per-batch
// softmax16k pipelined against per-batch stage-4 GEMM. The softmax is
// memory-bound and the GEMM tensor-bound (complementary resources, no added
// traffic); stage-4 per-batch is <1 wave so no quantization loss (the R12
// mistake was splitting a tensor-bound multi-wave GEMM instead).
// ---------------------------------------------------------------------------

#define BATCH 4
#define CDIM 512
#define NDIM 16384
#define KEYD 256

// fp16 buffers
__device__ __half g_featH[33554432];  // feat   [B,512,N]
__device__ __half g_pwH[33554432];    // softmax(feat) [B,512,N]
__device__ __half g_simH[33554432];   // sim    [B,N,512]
__device__ __half g_uH[33554432];     // ctx_up [B,512,N]
__device__ __half g_t1H[16777216];    // t1 [B,256,N]; later attn ctx
__device__ __half g_qH[16777216];     // q  [B,256,N]
__device__ __half g_ctxH[1048576];    // context [B,512,512]
__device__ __half g_cvH[1048576];     // [B, (c1:256 | v:256), 512]
__device__ __half g_kmH[524288];      // [B,256,512]
__device__ __half g_wH[1179648];      // converted weights (packed)
__device__ float g_biasCat[512];      // [bo1 ; bd]
__device__ float g_split[16777216];   // split-K partials

// ---------------------------------------------------------------------------
__device__ __forceinline__ void mma_f16(float c[4], const uint32_t a[4],
                                        const uint32_t b[2]) {
    asm volatile(
        "mma.sync.aligned.m16n8k16.row.col.f32.f16.f16.f32 "
        "{%0,%1,%2,%3}, {%4,%5,%6,%7}, {%8,%9}, {%0,%1,%2,%3};"
        : "+f"(c[0]), "+f"(c[1]), "+f"(c[2]), "+f"(c[3])
        : "r"(a[0]), "r"(a[1]), "r"(a[2]), "r"(a[3]), "r"(b[0]), "r"(b[1]));
}
__device__ __forceinline__ void cp16(uint32_t dst, const void* src) {
    asm volatile("cp.async.cg.shared.global [%0], [%1], 16;\n"
                 :: "r"(dst), "l"(src));
}
__device__ __forceinline__ void cp_commit() {
    asm volatile("cp.async.commit_group;\n" ::: "memory");
}
__device__ __forceinline__ void cp_wait0() {
    asm volatile("cp.async.wait_group 0;\n" ::: "memory");
}
__device__ __forceinline__ void cp_wait_all() {
    asm volatile("cp.async.wait_all;\n" ::: "memory");
}
__device__ __forceinline__ void ldsm_x4(uint32_t& r0, uint32_t& r1,
                                        uint32_t& r2, uint32_t& r3,
                                        uint32_t addr) {
    asm volatile("ldmatrix.sync.aligned.m8n8.x4.shared.b16 {%0,%1,%2,%3}, [%4];"
                 : "=r"(r0), "=r"(r1), "=r"(r2), "=r"(r3) : "r"(addr));
}
__device__ __forceinline__ void ldsm_x4_t(uint32_t& r0, uint32_t& r1,
                                          uint32_t& r2, uint32_t& r3,
                                          uint32_t addr) {
    asm volatile("ldmatrix.sync.aligned.m8n8.x4.trans.shared.b16 {%0,%1,%2,%3}, [%4];"
                 : "=r"(r0), "=r"(r1), "=r"(r2), "=r"(r3) : "r"(addr));
}

// ---------------------------------------------------------------------------
// fp16 batched GEMM (R9/R10 body): C[m,n]=act(alpha*sum_k opA*opB+bias[m]).
// TA: A [K,M] else [M,K]; TB: B [N,K] else [K,N]. CONCAT: B k>=ksplitB from B2.
// CTA 128x128, BK=64, 128 thr, warp tile 64x64, 2-stage cp.async + frag pipe.
// ---------------------------------------------------------------------------
template <bool TA, bool TB, bool CONCAT>
__global__ void __launch_bounds__(128, 2)
gemm_f16(const __half* __restrict__ A, size_t sA, int lda,
         const __half* __restrict__ B, size_t sB, int ldb,
         const __half* __restrict__ B2, int ksplitB,
         void* __restrict__ Cv, size_t sCz, int ldc,
         const float* __restrict__ bias, float alpha, int doRelu, int outHalf,
         int K, int nsplit) {
    constexpr int SA_ROW = 144;
    constexpr int SKM_ROW = 272;
    constexpr int ASZ = TA ? 64 * SKM_ROW : 128 * SA_ROW;
    constexpr int BSZ = TB ? 128 * SA_ROW : 64 * SKM_ROW;
    constexpr int STG = ASZ + BSZ;

    extern __shared__ __align__(16) char smem[];
    uint32_t base = (uint32_t)__cvta_generic_to_shared(smem);

    int z = blockIdx.z;
    int b = z / nsplit;
    int sidx = z - b * nsplit;
    int kchunk = K / nsplit;
    int kbeg = sidx * kchunk;
    int niter = kchunk >> 6;

    const __half* Ab = A + (size_t)b * sA;
    const __half* Bb = B + (size_t)b * sB;
    const __half* B2b = CONCAT ? (B2 + (size_t)b * sB) : (const __half*)nullptr;

    int m0 = blockIdx.y * 128;
    int n0 = blockIdx.x * 128;
    int tid = threadIdx.x;
    int warp = tid >> 5, lane = tid & 31;
    int g = lane >> 2, r = lane & 3;
    int wm = warp & 1, wn = warp >> 1;
    int warp_m0 = wm * 64, warp_n0 = wn * 64;

    int mo8 = (lane & 7) + ((lane >> 3) & 1) * 8;
    int khalf = lane >> 4;
    int kq = (lane & 7) + ((lane >> 4) & 1) * 8;
    int chalf = (lane >> 3) & 1;

    float acc[4][8][4];
    #pragma unroll
    for (int i = 0; i < 4; i++)
        #pragma unroll
        for (int j = 0; j < 8; j++)
            #pragma unroll
            for (int e = 0; e < 4; e++) acc[i][j][e] = 0.f;

    auto prefetch = [&](int st, int k0) {
        uint32_t ab = base + st * STG;
        uint32_t bb = ab + ASZ;
        if (TA) {
            #pragma unroll
            for (int p = 0; p < 8; p++) {
                int idx = tid + p * 128;
                int row = idx >> 4, mc = idx & 15;
                cp16(ab + row * SKM_ROW + mc * 16,
                     Ab + (size_t)(k0 + row) * lda + m0 + mc * 8);
            }
        } else {
            #pragma unroll
            for (int p = 0; p < 8; p++) {
                int idx = tid + p * 128;
                int row = idx >> 3, kc = idx & 7;
                cp16(ab + row * SA_ROW + kc * 16,
                     Ab + (size_t)(m0 + row) * lda + k0 + kc * 8);
            }
        }
        if (TB) {
            #pragma unroll
            for (int p = 0; p < 8; p++) {
                int idx = tid + p * 128;
                int row = idx >> 3, kc = idx & 7;
                cp16(bb + row * SA_ROW + kc * 16,
                     Bb + (size_t)(n0 + row) * ldb + k0 + kc * 8);
            }
        } else {
            #pragma unroll
            for (int p = 0; p < 8; p++) {
                int idx = tid + p * 128;
                int row = idx >> 4, nc = idx & 15;
                int kr = k0 + row;
                const __half* src;
                if (CONCAT && kr >= ksplitB)
                    src = B2b + (size_t)(kr - ksplitB) * ldb + n0 + nc * 8;
                else
                    src = Bb + (size_t)kr * ldb + n0 + nc * 8;
                cp16(bb + row * SKM_ROW + nc * 16, src);
            }
        }
        cp_commit();
    };

    prefetch(0, kbeg);

    uint32_t af[2][4][4], bf[2][8][2];

    for (int it = 0; it < niter; it++) {
        int st = it & 1;
        cp_wait0();
        __syncthreads();
        if (it + 1 < niter) prefetch(st ^ 1, kbeg + (it + 1) * 64);

        uint32_t ab = base + st * STG;
        uint32_t bb = ab + ASZ;

        auto load_frags = [&](int fb, int ks) {
            if (TA) {
                #pragma unroll
                for (int i = 0; i < 4; i++) {
                    uint32_t addr = ab + (ks * 16 + kq) * SKM_ROW +
                                    (warp_m0 + i * 16) * 2 + chalf * 16;
                    ldsm_x4_t(af[fb][i][0], af[fb][i][1],
                              af[fb][i][2], af[fb][i][3], addr);
                }
            } else {
                #pragma unroll
                for (int i = 0; i < 4; i++) {
                    uint32_t addr = ab + (warp_m0 + i * 16 + mo8) * SA_ROW +
                                    ks * 32 + khalf * 16;
                    ldsm_x4(af[fb][i][0], af[fb][i][1],
                            af[fb][i][2], af[fb][i][3], addr);
                }
            }
            if (TB) {
                #pragma unroll
                for (int jj = 0; jj < 4; jj++) {
                    uint32_t addr = bb + (warp_n0 + jj * 16 + mo8) * SA_ROW +
                                    ks * 32 + khalf * 16;
                    ldsm_x4(bf[fb][2 * jj][0], bf[fb][2 * jj + 1][0],
                            bf[fb][2 * jj][1], bf[fb][2 * jj + 1][1], addr);
                }
            } else {
                #pragma unroll
                for (int jj = 0; jj < 4; jj++) {
                    uint32_t addr = bb + (ks * 16 + kq) * SKM_ROW +
                                    (warp_n0 + jj * 16) * 2 + chalf * 16;
                    ldsm_x4_t(bf[fb][2 * jj][0], bf[fb][2 * jj + 1][0],
                              bf[fb][2 * jj][1], bf[fb][2 * jj + 1][1], addr);
                }
            }
        };

        load_frags(0, 0);
        #pragma unroll
        for (int ks = 0; ks < 4; ks++) {
            int cur = ks & 1;
            if (ks < 3) load_frags(cur ^ 1, ks + 1);
            #pragma unroll
            for (int i = 0; i < 4; i++)
                #pragma unroll
                for (int j = 0; j < 8; j++)
                    mma_f16(acc[i][j], af[cur][i], bf[cur][j]);
        }
        __syncthreads();
    }

    cp_wait_all();

    __half* Ch = (__half*)Cv + (size_t)z * sCz;
    float* Cf = (float*)Cv + (size_t)z * sCz;
    #pragma unroll
    for (int i = 0; i < 4; i++) {
        int m = m0 + warp_m0 + i * 16 + g;
        float bv0 = bias ? bias[m] : 0.f;
        float bv8 = bias ? bias[m + 8] : 0.f;
        #pragma unroll
        for (int j = 0; j < 8; j++) {
            int n = n0 + warp_n0 + j * 8 + 2 * r;
            float x0 = acc[i][j][0] * alpha + bv0;
            float x1 = acc[i][j][1] * alpha + bv0;
            float x2 = acc[i][j][2] * alpha + bv8;
            float x3 = acc[i][j][3] * alpha + bv8;
            if (doRelu) {
                x0 = fmaxf(x0, 0.f); x1 = fmaxf(x1, 0.f);
                x2 = fmaxf(x2, 0.f); x3 = fmaxf(x3, 0.f);
            }
            if (outHalf) {
                *(__half2*)&Ch[(size_t)m * ldc + n] = __floats2half2_rn(x0, x1);
                *(__half2*)&Ch[(size_t)(m + 8) * ldc + n] = __floats2half2_rn(x2, x3);
            } else {
                *(float2*)&Cf[(size_t)m * ldc + n] = make_float2(x0, x1);
                *(float2*)&Cf[(size_t)(m + 8) * ldc + n] = make_float2(x2, x3);
            }
        }
    }
}

// ---------------------------------------------------------------------------
// softmax over rows of 16384: emits fp16 softmax AND fp16 copy of input.
// Launched per batch (grid = 512 rows).
__global__ void softmax_rows16k(const float* __restrict__ x,
                                __half* __restrict__ pwout,
                                __half* __restrict__ xh) {
    extern __shared__ float srow[];
    __shared__ float red[256];
    const int NC = NDIM;
    size_t row = blockIdx.x;
    const float* xr = x + row * (size_t)NC;
    __half* pwr = pwout + row * (size_t)NC;
    __half* xhr = xh + row * (size_t)NC;
    int tid = threadIdx.x;

    float m = -3.4e38f;
    for (int i = tid * 4; i < NC; i += 1024) {
        float4 v = *(const float4*)&xr[i];
        *(float4*)&srow[i] = v;
        *(__half2*)&xhr[i] = __floats2half2_rn(v.x, v.y);
        *(__half2*)&xhr[i + 2] = __floats2half2_rn(v.z, v.w);
        m = fmaxf(m, fmaxf(fmaxf(v.x, v.y), fmaxf(v.z, v.w)));
    }
    red[tid] = m;
    __syncthreads();
    for (int s = 128; s > 0; s >>= 1) {
        if (tid < s) red[tid] = fmaxf(red[tid], red[tid + s]);
        __syncthreads();
    }
    m = red[0];
    __syncthreads();

    float sum = 0.f;
    for (int i = tid * 4; i < NC; i += 1024) {
        float4 v = *(float4*)&srow[i];
        v.x = __expf(v.x - m); v.y = __expf(v.y - m);
        v.z = __expf(v.z - m); v.w = __expf(v.w - m);
        *(float4*)&srow[i] = v;
        sum += v.x + v.y + v.z + v.w;
    }
    red[tid] = sum;
    __syncthreads();
    for (int s = 128; s > 0; s >>= 1) {
        if (tid < s) red[tid] += red[tid + s];
        __syncthreads();
    }
    float inv = 1.f / red[0];

    for (int i = tid * 4; i < NC; i += 1024) {
        float4 v = *(float4*)&srow[i];
        *(__half2*)&pwr[i] = __floats2half2_rn(v.x * inv, v.y * inv);
        *(__half2*)&pwr[i + 2] = __floats2half2_rn(v.z * inv, v.w * inv);
    }
}

__global__ void softmax_k512h(__half* __restrict__ sim) {
    __shared__ float redm[4];
    __shared__ float reds[4];
    size_t row = blockIdx.x;
    __half2* rp = (__half2*)(sim + row * 512);
    int tid = threadIdx.x;

    __half2 h0 = rp[tid * 2], h1 = rp[tid * 2 + 1];
    float2 f0 = __half22float2(h0), f1 = __half22float2(h1);
    float m = fmaxf(fmaxf(f0.x, f0.y), fmaxf(f1.x, f1.y));
    #pragma unroll
    for (int o = 16; o > 0; o >>= 1)
        m = fmaxf(m, __shfl_xor_sync(0xffffffffu, m, o));
    if ((tid & 31) == 0) redm[tid >> 5] = m;
    __syncthreads();
    m = fmaxf(fmaxf(redm[0], redm[1]), fmaxf(redm[2], redm[3]));

    float e0 = __expf(f0.x - m), e1 = __expf(f0.y - m);
    float e2 = __expf(f1.x - m), e3 = __expf(f1.y - m);
    float s = e0 + e1 + e2 + e3;
    #pragma unroll
    for (int o = 16; o > 0; o >>= 1)
        s += __shfl_xor_sync(0xffffffffu, s, o);
    if ((tid & 31) == 0) reds[tid >> 5] = s;
    __syncthreads();
    float inv = 1.f / (reds[0] + reds[1] + reds[2] + reds[3]);

    rp[tid * 2] = __floats2half2_rn(e0 * inv, e1 * inv);
    rp[tid * 2 + 1] = __floats2half2_rn(e2 * inv, e3 * inv);
}

__global__ void reduce_split(const float* __restrict__ in,
                             __half* __restrict__ out, int per, int nsplit,
                             size_t total) {
    size_t i = (size_t)blockIdx.x * blockDim.x + threadIdx.x;
    if (i >= total) return;
    size_t b = i / per;
    size_t r = i - b * per;
    const float* src = in + b * (size_t)nsplit * per + r;
    float s = 0.f;
    for (int ss = 0; ss < nsplit; ss++) s += src[(size_t)ss * per];
    out[i] = __float2half_rn(s);
}

// fp32->fp16 all weights (packed: wp1|wp2|(wo1;wd)|wo2|wu|wout) + bias concat.
__global__ void convert_weights(const float* __restrict__ wp1,
                                const float* __restrict__ wp2,
                                const float* __restrict__ wo1,
                                const float* __restrict__ wo2,
                                const float* __restrict__ wd,
                                const float* __restrict__ wu,
                                const float* __restrict__ wout,
                                const float* __restrict__ bo1,
                                const float* __restrict__ bd,
                                __half* __restrict__ out,
                                float* __restrict__ bcat) {
    int t = blockIdx.x * blockDim.x + threadIdx.x;
    if (t < 256) bcat[t] = bo1[t];
    else if (t < 512) bcat[t] = bd[t - 256];
    int i = t * 4;
    if (i >= 1179648) return;
    const float* src;
    int local;
    if (i < 131072)      { src = wp1;  local = i; }
    else if (i < 196608) { src = wp2;  local = i - 131072; }
    else if (i < 327680) { src = wo1;  local = i - 196608; }
    else if (i < 458752) { src = wd;   local = i - 327680; }
    else if (i < 524288) { src = wo2;  local = i - 458752; }
    else if (i < 655360) { src = wu;   local = i - 524288; }
    else                 { src = wout; local = i - 655360; }
    float4 v = *(const float4*)&src[local];
    *(__half2*)&out[i] = __floats2half2_rn(v.x, v.y);
    *(__half2*)&out[i + 2] = __floats2half2_rn(v.z, v.w);
}

// ---------------------------------------------------------------------------
static constexpr int SM_FF = 2 * (128 * 144 + 64 * 272);   // 71680
static constexpr int SM_FT = 2 * (128 * 144 + 128 * 144);  // 73728
static constexpr int SM_TF = 2 * (64 * 272 + 64 * 272);    // 69632

extern "C" void kernel_launch(void* const* d_in, const int* in_sizes, int n_in,
                              void* d_out, int out_size) {
    (void)in_sizes; (void)n_in; (void)out_size;
    const float* feat = (const float*)d_in[0];
    const float* wp1 = (const float*)d_in[2];
    const float* bp1 = (const float*)d_in[3];
    const float* wp2 = (const float*)d_in[4];
    const float* bp2 = (const float*)d_in[5];
    const float* wo1 = (const float*)d_in[6];
    const float* bo1 = (const float*)d_in[7];
    const float* wo2 = (const float*)d_in[8];
    const float* bo2 = (const float*)d_in[9];
    const float* wd  = (const float*)d_in[10];
    const float* bd  = (const float*)d_in[11];
    const float* wu  = (const float*)d_in[12];
    const float* bu  = (const float*)d_in[13];
    const float* wout = (const float*)d_in[14];
    const float* bout = (const float*)d_in[15];
    float* outp = (float*)d_out;

    __half *featH, *pwH, *simH, *uH, *t1H, *qH, *ctxH, *cvH, *kmH, *wH;
    float *splitF, *bcat;
    cudaGetSymbolAddress((void**)&featH, g_featH);
    cudaGetSymbolAddress((void**)&pwH, g_pwH);
    cudaGetSymbolAddress((void**)&simH, g_simH);
    cudaGetSymbolAddress((void**)&uH, g_uH);
    cudaGetSymbolAddress((void**)&t1H, g_t1H);
    cudaGetSymbolAddress((void**)&qH, g_qH);
    cudaGetSymbolAddress((void**)&ctxH, g_ctxH);
    cudaGetSymbolAddress((void**)&cvH, g_cvH);
    cudaGetSymbolAddress((void**)&kmH, g_kmH);
    cudaGetSymbolAddress((void**)&wH, g_wH);
    cudaGetSymbolAddress((void**)&splitF, g_split);
    cudaGetSymbolAddress((void**)&bcat, g_biasCat);
    __half* wp1H = wH;               // 131072
    __half* wp2H = wH + 131072;      // 65536
    __half* wcatH = wH + 196608;     // 262144 (wo1 rows 0-255 | wd rows 256-511)
    __half* wo2H = wH + 458752;      // 65536
    __half* wuH  = wH + 524288;      // 131072
    __half* woutH = wH + 655360;     // 524288

    const size_t sBN = (size_t)CDIM * NDIM;
    const size_t sKN = (size_t)KEYD * NDIM;
    const size_t sCC = (size_t)CDIM * CDIM;
    const size_t sKC = (size_t)KEYD * CDIM;

    static cudaStream_t sCtx = nullptr;
    static cudaEvent_t evW = nullptr, evJoinCtx = nullptr;
    static cudaEvent_t evSm[BATCH] = {nullptr, nullptr, nullptr, nullptr};
    if (sCtx == nullptr) {
        cudaStreamCreateWithFlags(&sCtx, cudaStreamNonBlocking);
        cudaEventCreateWithFlags(&evW, cudaEventDisableTiming);
        cudaEventCreateWithFlags(&evJoinCtx, cudaEventDisableTiming);
        for (int b = 0; b < BATCH; b++)
            cudaEventCreateWithFlags(&evSm[b], cudaEventDisableTiming);
    }

    cudaFuncSetAttribute(softmax_rows16k,
                         cudaFuncAttributeMaxDynamicSharedMemorySize, 65536);
    cudaFuncSetAttribute(gemm_f16<false, false, false>,
                         cudaFuncAttributeMaxDynamicSharedMemorySize, SM_FF);
    cudaFuncSetAttribute(gemm_f16<false, false, true>,
                         cudaFuncAttributeMaxDynamicSharedMemorySize, SM_FF);
    cudaFuncSetAttribute(gemm_f16<false, true, false>,
                         cudaFuncAttributeMaxDynamicSharedMemorySize, SM_FT);
    cudaFuncSetAttribute(gemm_f16<true, false, false>,
                         cudaFuncAttributeMaxDynamicSharedMemorySize, SM_TF);

    // [s0] weights + bias concat
    convert_weights<<<1152, 256>>>(wp1, wp2, wo1, wo2, wd, wu, wout,
                                   bo1, bd, wH, bcat);
    cudaEventRecord(evW, 0);

    // [sCtx] per-batch softmax16k (memory-bound); each batch signals its
    // event so the tensor-bound stage-4 GEMM of batch b overlaps softmax b+1.
    cudaStreamWaitEvent(sCtx, evW, 0);
    for (int b = 0; b < BATCH; b++) {
        softmax_rows16k<<<CDIM, 256, 65536, sCtx>>>(
            feat + (size_t)b * sBN, pwH + (size_t)b * sBN,
            featH + (size_t)b * sBN);
        cudaEventRecord(evSm[b], sCtx);
    }

    // [s0] stage 4 per batch: t1_b = relu(wp1 @ x_b + bp1)
    for (int b = 0; b < BATCH; b++) {
        cudaStreamWaitEvent(0, evSm[b], 0);
        gemm_f16<false, false, false><<<dim3(128, 2, 1), 128, SM_FF>>>(
            wp1H, 0, CDIM, featH + (size_t)b * sBN, 0, NDIM, nullptr, 0,
            t1H + (size_t)b * sKN, 0, NDIM, bp1, 1.f, 1, 1, CDIM, 1);
    }

    // [sCtx] context chain (after all softmaxes, same stream order)
    gemm_f16<false, true, false><<<dim3(4, 4, BATCH * 4), 128, SM_FT, sCtx>>>(
        featH, sBN, NDIM, pwH, sBN, NDIM, nullptr, 0,
        splitF, sCC, CDIM, nullptr, 1.f, 0, 0, NDIM, 4);
    {
        size_t total = (size_t)BATCH * sCC;
        reduce_split<<<(unsigned)((total + 255) / 256), 256, 0, sCtx>>>(
            splitF, ctxH, (int)sCC, 4, total);
    }
    gemm_f16<false, false, false><<<dim3(4, 4, BATCH), 128, SM_FF, sCtx>>>(
        wcatH, 0, CDIM, ctxH, sCC, CDIM, nullptr, 0,
        cvH, sCC, CDIM, bcat, 1.f, 1, 1, CDIM, 1);
    gemm_f16<false, false, false><<<dim3(4, 2, BATCH), 128, SM_FF, sCtx>>>(
        wo2H, 0, KEYD, cvH, sCC, CDIM, nullptr, 0,
        kmH, sKC, CDIM, bo2, 1.f, 1, 1, KEYD, 1);
    cudaEventRecord(evJoinCtx, sCtx);

    // [s0] stage 5 (monolithic): q = relu(wp2 @ t1 + bp2)
    gemm_f16<false, false, false><<<dim3(128, 2, BATCH), 128, SM_FF>>>(
        wp2H, 0, KEYD, t1H, sKN, NDIM, nullptr, 0,
        qH, sKN, NDIM, bp2, 1.f, 1, 1, KEYD, 1);

    // ---- join ctx chain ----
    cudaStreamWaitEvent(0, evJoinCtx, 0);

    // [s0] sim = (q^T @ km) * KEY^-0.5 (monolithic, R10 tail)
    gemm_f16<true, false, false><<<dim3(4, 128, BATCH), 128, SM_TF>>>(
        qH, sKN, NDIM, kmH, sKC, CDIM, nullptr, 0,
        simH, sBN, CDIM, nullptr, 0.0625f, 0, 1, KEYD, 1);
    softmax_k512h<<<BATCH * NDIM, 128>>>(simH);
    gemm_f16<false, true, false><<<dim3(128, 2, BATCH), 128, SM_FT>>>(
        cvH + 131072, sCC, CDIM, simH, sBN, CDIM, nullptr, 0,
        t1H, sKN, NDIM, nullptr, 1.f, 0, 1, CDIM, 1);
    gemm_f16<false, false, false><<<dim3(128, 4, BATCH), 128, SM_FF>>>(
        wuH, 0, KEYD, t1H, sKN, NDIM, nullptr, 0,
        uH, sBN, NDIM, bu, 1.f, 1, 1, KEYD, 1);
    gemm_f16<false, false, true><<<dim3(128, 4, BATCH), 128, SM_FF>>>(
        woutH, 0, 2 * CDIM, uH, sBN, NDIM, featH, CDIM,
        outp, sBN, NDIM, bout, 1.f, 1, 0, 2 * CDIM, 1);
}

// round 14
// speedup vs baseline: 1.0592x; 1.0592x over previous
#include <cuda_runtime.h>
#include <cuda_fp16.h>
#include <cstdint>
#include <cstddef>

// ---------------------------------------------------------------------------
// OCR head on GB300 — Round 14: exact R10 schedule (best, 774.6us) with the
// softmax16k kernel rebuilt: fp16 smem row (32KB) + 512 threads -> 64
// warps/SM (was 24), fixing its measured occupancy/latency bound
// (ncu: DRAM 15.7%, occ 32.2%). No scheduling changes (R11-13 all lost).
// ---------------------------------------------------------------------------

#define BATCH 4
#define CDIM 512
#define NDIM 16384
#define KEYD 256

// fp16 buffers
__device__ __half g_featH[33554432];  // feat   [B,512,N]
__device__ __half g_pwH[33554432];    // softmax(feat) [B,512,N]
__device__ __half g_simH[33554432];   // sim    [B,N,512]
__device__ __half g_uH[33554432];     // ctx_up [B,512,N]
__device__ __half g_t1H[16777216];    // t1 [B,256,N]; later attn ctx
__device__ __half g_qH[16777216];     // q  [B,256,N]
__device__ __half g_ctxH[1048576];    // context [B,512,512]
__device__ __half g_cvH[1048576];     // [B, (c1:256 | v:256), 512]
__device__ __half g_kmH[524288];      // [B,256,512]
__device__ __half g_wH[1179648];      // converted weights (packed)
__device__ float g_biasCat[512];      // [bo1 ; bd]
__device__ float g_split[16777216];   // split-K partials

// ---------------------------------------------------------------------------
__device__ __forceinline__ void mma_f16(float c[4], const uint32_t a[4],
                                        const uint32_t b[2]) {
    asm volatile(
        "mma.sync.aligned.m16n8k16.row.col.f32.f16.f16.f32 "
        "{%0,%1,%2,%3}, {%4,%5,%6,%7}, {%8,%9}, {%0,%1,%2,%3};"
        : "+f"(c[0]), "+f"(c[1]), "+f"(c[2]), "+f"(c[3])
        : "r"(a[0]), "r"(a[1]), "r"(a[2]), "r"(a[3]), "r"(b[0]), "r"(b[1]));
}
__device__ __forceinline__ void cp16(uint32_t dst, const void* src) {
    asm volatile("cp.async.cg.shared.global [%0], [%1], 16;\n"
                 :: "r"(dst), "l"(src));
}
__device__ __forceinline__ void cp_commit() {
    asm volatile("cp.async.commit_group;\n" ::: "memory");
}
__device__ __forceinline__ void cp_wait0() {
    asm volatile("cp.async.wait_group 0;\n" ::: "memory");
}
__device__ __forceinline__ void cp_wait_all() {
    asm volatile("cp.async.wait_all;\n" ::: "memory");
}
__device__ __forceinline__ void ldsm_x4(uint32_t& r0, uint32_t& r1,
                                        uint32_t& r2, uint32_t& r3,
                                        uint32_t addr) {
    asm volatile("ldmatrix.sync.aligned.m8n8.x4.shared.b16 {%0,%1,%2,%3}, [%4];"
                 : "=r"(r0), "=r"(r1), "=r"(r2), "=r"(r3) : "r"(addr));
}
__device__ __forceinline__ void ldsm_x4_t(uint32_t& r0, uint32_t& r1,
                                          uint32_t& r2, uint32_t& r3,
                                          uint32_t addr) {
    asm volatile("ldmatrix.sync.aligned.m8n8.x4.trans.shared.b16 {%0,%1,%2,%3}, [%4];"
                 : "=r"(r0), "=r"(r1), "=r"(r2), "=r"(r3) : "r"(addr));
}

// ---------------------------------------------------------------------------
// fp16 batched GEMM (R9/R10 body): C[m,n]=act(alpha*sum_k opA*opB+bias[m]).
// TA: A [K,M] else [M,K]; TB: B [N,K] else [K,N]. CONCAT: B k>=ksplitB from B2.
// CTA 128x128, BK=64, 128 thr, warp tile 64x64, 2-stage cp.async + frag pipe.
// ---------------------------------------------------------------------------
template <bool TA, bool TB, bool CONCAT>
__global__ void __launch_bounds__(128, 2)
gemm_f16(const __half* __restrict__ A, size_t sA, int lda,
         const __half* __restrict__ B, size_t sB, int ldb,
         const __half* __restrict__ B2, int ksplitB,
         void* __restrict__ Cv, size_t sCz, int ldc,
         const float* __restrict__ bias, float alpha, int doRelu, int outHalf,
         int K, int nsplit) {
    constexpr int SA_ROW = 144;
    constexpr int SKM_ROW = 272;
    constexpr int ASZ = TA ? 64 * SKM_ROW : 128 * SA_ROW;
    constexpr int BSZ = TB ? 128 * SA_ROW : 64 * SKM_ROW;
    constexpr int STG = ASZ + BSZ;

    extern __shared__ __align__(16) char smem[];
    uint32_t base = (uint32_t)__cvta_generic_to_shared(smem);

    int z = blockIdx.z;
    int b = z / nsplit;
    int sidx = z - b * nsplit;
    int kchunk = K / nsplit;
    int kbeg = sidx * kchunk;
    int niter = kchunk >> 6;

    const __half* Ab = A + (size_t)b * sA;
    const __half* Bb = B + (size_t)b * sB;
    const __half* B2b = CONCAT ? (B2 + (size_t)b * sB) : (const __half*)nullptr;

    int m0 = blockIdx.y * 128;
    int n0 = blockIdx.x * 128;
    int tid = threadIdx.x;
    int warp = tid >> 5, lane = tid & 31;
    int g = lane >> 2, r = lane & 3;
    int wm = warp & 1, wn = warp >> 1;
    int warp_m0 = wm * 64, warp_n0 = wn * 64;

    int mo8 = (lane & 7) + ((lane >> 3) & 1) * 8;
    int khalf = lane >> 4;
    int kq = (lane & 7) + ((lane >> 4) & 1) * 8;
    int chalf = (lane >> 3) & 1;

    float acc[4][8][4];
    #pragma unroll
    for (int i = 0; i < 4; i++)
        #pragma unroll
        for (int j = 0; j < 8; j++)
            #pragma unroll
            for (int e = 0; e < 4; e++) acc[i][j][e] = 0.f;

    auto prefetch = [&](int st, int k0) {
        uint32_t ab = base + st * STG;
        uint32_t bb = ab + ASZ;
        if (TA) {
            #pragma unroll
            for (int p = 0; p < 8; p++) {
                int idx = tid + p * 128;
                int row = idx >> 4, mc = idx & 15;
                cp16(ab + row * SKM_ROW + mc * 16,
                     Ab + (size_t)(k0 + row) * lda + m0 + mc * 8);
            }
        } else {
            #pragma unroll
            for (int p = 0; p < 8; p++) {
                int idx = tid + p * 128;
                int row = idx >> 3, kc = idx & 7;
                cp16(ab + row * SA_ROW + kc * 16,
                     Ab + (size_t)(m0 + row) * lda + k0 + kc * 8);
            }
        }
        if (TB) {
            #pragma unroll
            for (int p = 0; p < 8; p++) {
                int idx = tid + p * 128;
                int row = idx >> 3, kc = idx & 7;
                cp16(bb + row * SA_ROW + kc * 16,
                     Bb + (size_t)(n0 + row) * ldb + k0 + kc * 8);
            }
        } else {
            #pragma unroll
            for (int p = 0; p < 8; p++) {
                int idx = tid + p * 128;
                int row = idx >> 4, nc = idx & 15;
                int kr = k0 + row;
                const __half* src;
                if (CONCAT && kr >= ksplitB)
                    src = B2b + (size_t)(kr - ksplitB) * ldb + n0 + nc * 8;
                else
                    src = Bb + (size_t)kr * ldb + n0 + nc * 8;
                cp16(bb + row * SKM_ROW + nc * 16, src);
            }
        }
        cp_commit();
    };

    prefetch(0, kbeg);

    uint32_t af[2][4][4], bf[2][8][2];

    for (int it = 0; it < niter; it++) {
        int st = it & 1;
        cp_wait0();
        __syncthreads();
        if (it + 1 < niter) prefetch(st ^ 1, kbeg + (it + 1) * 64);

        uint32_t ab = base + st * STG;
        uint32_t bb = ab + ASZ;

        auto load_frags = [&](int fb, int ks) {
            if (TA) {
                #pragma unroll
                for (int i = 0; i < 4; i++) {
                    uint32_t addr = ab + (ks * 16 + kq) * SKM_ROW +
                                    (warp_m0 + i * 16) * 2 + chalf * 16;
                    ldsm_x4_t(af[fb][i][0], af[fb][i][1],
                              af[fb][i][2], af[fb][i][3], addr);
                }
            } else {
                #pragma unroll
                for (int i = 0; i < 4; i++) {
                    uint32_t addr = ab + (warp_m0 + i * 16 + mo8) * SA_ROW +
                                    ks * 32 + khalf * 16;
                    ldsm_x4(af[fb][i][0], af[fb][i][1],
                            af[fb][i][2], af[fb][i][3], addr);
                }
            }
            if (TB) {
                #pragma unroll
                for (int jj = 0; jj < 4; jj++) {
                    uint32_t addr = bb + (warp_n0 + jj * 16 + mo8) * SA_ROW +
                                    ks * 32 + khalf * 16;
                    ldsm_x4(bf[fb][2 * jj][0], bf[fb][2 * jj + 1][0],
                            bf[fb][2 * jj][1], bf[fb][2 * jj + 1][1], addr);
                }
            } else {
                #pragma unroll
                for (int jj = 0; jj < 4; jj++) {
                    uint32_t addr = bb + (ks * 16 + kq) * SKM_ROW +
                                    (warp_n0 + jj * 16) * 2 + chalf * 16;
                    ldsm_x4_t(bf[fb][2 * jj][0], bf[fb][2 * jj + 1][0],
                              bf[fb][2 * jj][1], bf[fb][2 * jj + 1][1], addr);
                }
            }
        };

        load_frags(0, 0);
        #pragma unroll
        for (int ks = 0; ks < 4; ks++) {
            int cur = ks & 1;
            if (ks < 3) load_frags(cur ^ 1, ks + 1);
            #pragma unroll
            for (int i = 0; i < 4; i++)
                #pragma unroll
                for (int j = 0; j < 8; j++)
                    mma_f16(acc[i][j], af[cur][i], bf[cur][j]);
        }
        __syncthreads();
    }

    cp_wait_all();

    __half* Ch = (__half*)Cv + (size_t)z * sCz;
    float* Cf = (float*)Cv + (size_t)z * sCz;
    #pragma unroll
    for (int i = 0; i < 4; i++) {
        int m = m0 + warp_m0 + i * 16 + g;
        float bv0 = bias ? bias[m] : 0.f;
        float bv8 = bias ? bias[m + 8] : 0.f;
        #pragma unroll
        for (int j = 0; j < 8; j++) {
            int n = n0 + warp_n0 + j * 8 + 2 * r;
            float x0 = acc[i][j][0] * alpha + bv0;
            float x1 = acc[i][j][1] * alpha + bv0;
            float x2 = acc[i][j][2] * alpha + bv8;
            float x3 = acc[i][j][3] * alpha + bv8;
            if (doRelu) {
                x0 = fmaxf(x0, 0.f); x1 = fmaxf(x1, 0.f);
                x2 = fmaxf(x2, 0.f); x3 = fmaxf(x3, 0.f);
            }
            if (outHalf) {
                *(__half2*)&Ch[(size_t)m * ldc + n] = __floats2half2_rn(x0, x1);
                *(__half2*)&Ch[(size_t)(m + 8) * ldc + n] = __floats2half2_rn(x2, x3);
            } else {
                *(float2*)&Cf[(size_t)m * ldc + n] = make_float2(x0, x1);
                *(float2*)&Cf[(size_t)(m + 8) * ldc + n] = make_float2(x2, x3);
            }
        }
    }
}

// ---------------------------------------------------------------------------
// softmax over rows of 16384, high-occupancy version:
// fp16 smem row (32KB) + 512 threads -> 4 CTAs/SM, 64 warps/SM.
// Max computed from fp32; exp from fp16-rounded values (error analyzed ok).
__global__ void __launch_bounds__(512)
softmax_rows16k(const float* __restrict__ x,
                __half* __restrict__ pwout,
                __half* __restrict__ xh) {
    __shared__ __half srow[NDIM];     // 32KB
    __shared__ float red[512];
    size_t row = blockIdx.x;
    const float* xr = x + row * (size_t)NDIM;
    __half* pwr = pwout + row * (size_t)NDIM;
    __half* xhr = xh + row * (size_t)NDIM;
    int tid = threadIdx.x;

    float m = -3.4e38f;
    for (int i = tid * 4; i < NDIM; i += 2048) {
        float4 v = *(const float4*)&xr[i];
        __half2 h01 = __floats2half2_rn(v.x, v.y);
        __half2 h23 = __floats2half2_rn(v.z, v.w);
        *(__half2*)&srow[i] = h01;
        *(__half2*)&srow[i + 2] = h23;
        *(__half2*)&xhr[i] = h01;
        *(__half2*)&xhr[i + 2] = h23;
        m = fmaxf(m, fmaxf(fmaxf(v.x, v.y), fmaxf(v.z, v.w)));
    }
    red[tid] = m;
    __syncthreads();
    for (int s = 256; s > 0; s >>= 1) {
        if (tid < s) red[tid] = fmaxf(red[tid], red[tid + s]);
        __syncthreads();
    }
    m = red[0];
    __syncthreads();

    float sum = 0.f;
    for (int i = tid * 4; i < NDIM; i += 2048) {
        float2 a = __half22float2(*(__half2*)&srow[i]);
        float2 b = __half22float2(*(__half2*)&srow[i + 2]);
        float e0 = __expf(a.x - m), e1 = __expf(a.y - m);
        float e2 = __expf(b.x - m), e3 = __expf(b.y - m);
        *(__half2*)&srow[i] = __floats2half2_rn(e0, e1);
        *(__half2*)&srow[i + 2] = __floats2half2_rn(e2, e3);
        sum += e0 + e1 + e2 + e3;
    }
    red[tid] = sum;
    __syncthreads();
    for (int s = 256; s > 0; s >>= 1) {
        if (tid < s) red[tid] += red[tid + s];
        __syncthreads();
    }
    float inv = 1.f / red[0];

    for (int i = tid * 4; i < NDIM; i += 2048) {
        float2 a = __half22float2(*(__half2*)&srow[i]);
        float2 b = __half22float2(*(__half2*)&srow[i + 2]);
        *(__half2*)&pwr[i] = __floats2half2_rn(a.x * inv, a.y * inv);
        *(__half2*)&pwr[i + 2] = __floats2half2_rn(b.x * inv, b.y * inv);
    }
}

__global__ void softmax_k512h(__half* __restrict__ sim) {
    __shared__ float redm[4];
    __shared__ float reds[4];
    size_t row = blockIdx.x;
    __half2* rp = (__half2*)(sim + row * 512);
    int tid = threadIdx.x;

    __half2 h0 = rp[tid * 2], h1 = rp[tid * 2 + 1];
    float2 f0 = __half22float2(h0), f1 = __half22float2(h1);
    float m = fmaxf(fmaxf(f0.x, f0.y), fmaxf(f1.x, f1.y));
    #pragma unroll
    for (int o = 16; o > 0; o >>= 1)
        m = fmaxf(m, __shfl_xor_sync(0xffffffffu, m, o));
    if ((tid & 31) == 0) redm[tid >> 5] = m;
    __syncthreads();
    m = fmaxf(fmaxf(redm[0], redm[1]), fmaxf(redm[2], redm[3]));

    float e0 = __expf(f0.x - m), e1 = __expf(f0.y - m);
    float e2 = __expf(f1.x - m), e3 = __expf(f1.y - m);
    float s = e0 + e1 + e2 + e3;
    #pragma unroll
    for (int o = 16; o > 0; o >>= 1)
        s += __shfl_xor_sync(0xffffffffu, s, o);
    if ((tid & 31) == 0) reds[tid >> 5] = s;
    __syncthreads();
    float inv = 1.f / (reds[0] + reds[1] + reds[2] + reds[3]);

    rp[tid * 2] = __floats2half2_rn(e0 * inv, e1 * inv);
    rp[tid * 2 + 1] = __floats2half2_rn(e2 * inv, e3 * inv);
}

__global__ void reduce_split(const float* __restrict__ in,
                             __half* __restrict__ out, int per, int nsplit,
                             size_t total) {
    size_t i = (size_t)blockIdx.x * blockDim.x + threadIdx.x;
    if (i >= total) return;
    size_t b = i / per;
    size_t r = i - b * per;
    const float* src = in + b * (size_t)nsplit * per + r;
    float s = 0.f;
    for (int ss = 0; ss < nsplit; ss++) s += src[(size_t)ss * per];
    out[i] = __float2half_rn(s);
}

// fp32->fp16 all weights (packed: wp1|wp2|(wo1;wd)|wo2|wu|wout) + bias concat.
__global__ void convert_weights(const float* __restrict__ wp1,
                                const float* __restrict__ wp2,
                                const float* __restrict__ wo1,
                                const float* __restrict__ wo2,
                                const float* __restrict__ wd,
                                const float* __restrict__ wu,
                                const float* __restrict__ wout,
                                const float* __restrict__ bo1,
                                const float* __restrict__ bd,
                                __half* __restrict__ out,
                                float* __restrict__ bcat) {
    int t = blockIdx.x * blockDim.x + threadIdx.x;
    if (t < 256) bcat[t] = bo1[t];
    else if (t < 512) bcat[t] = bd[t - 256];
    int i = t * 4;
    if (i >= 1179648) return;
    const float* src;
    int local;
    if (i < 131072)      { src = wp1;  local = i; }
    else if (i < 196608) { src = wp2;  local = i - 131072; }
    else if (i < 327680) { src = wo1;  local = i - 196608; }
    else if (i < 458752) { src = wd;   local = i - 327680; }
    else if (i < 524288) { src = wo2;  local = i - 458752; }
    else if (i < 655360) { src = wu;   local = i - 524288; }
    else                 { src = wout; local = i - 655360; }
    float4 v = *(const float4*)&src[local];
    *(__half2*)&out[i] = __floats2half2_rn(v.x, v.y);
    *(__half2*)&out[i + 2] = __floats2half2_rn(v.z, v.w);
}

// ---------------------------------------------------------------------------
static constexpr int SM_FF = 2 * (128 * 144 + 64 * 272);   // 71680
static constexpr int SM_FT = 2 * (128 * 144 + 128 * 144);  // 73728
static constexpr int SM_TF = 2 * (64 * 272 + 64 * 272);    // 69632

extern "C" void kernel_launch(void* const* d_in, const int* in_sizes, int n_in,
                              void* d_out, int out_size) {
    (void)in_sizes; (void)n_in; (void)out_size;
    const float* feat = (const float*)d_in[0];
    const float* wp1 = (const float*)d_in[2];
    const float* bp1 = (const float*)d_in[3];
    const float* wp2 = (const float*)d_in[4];
    const float* bp2 = (const float*)d_in[5];
    const float* wo1 = (const float*)d_in[6];
    const float* bo1 = (const float*)d_in[7];
    const float* wo2 = (const float*)d_in[8];
    const float* bo2 = (const float*)d_in[9];
    const float* wd  = (const float*)d_in[10];
    const float* bd  = (const float*)d_in[11];
    const float* wu  = (const float*)d_in[12];
    const float* bu  = (const float*)d_in[13];
    const float* wout = (const float*)d_in[14];
    const float* bout = (const float*)d_in[15];
    float* outp = (float*)d_out;

    __half *featH, *pwH, *simH, *uH, *t1H, *qH, *ctxH, *cvH, *kmH, *wH;
    float *splitF, *bcat;
    cudaGetSymbolAddress((void**)&featH, g_featH);
    cudaGetSymbolAddress((void**)&pwH, g_pwH);
    cudaGetSymbolAddress((void**)&simH, g_simH);
    cudaGetSymbolAddress((void**)&uH, g_uH);
    cudaGetSymbolAddress((void**)&t1H, g_t1H);
    cudaGetSymbolAddress((void**)&qH, g_qH);
    cudaGetSymbolAddress((void**)&ctxH, g_ctxH);
    cudaGetSymbolAddress((void**)&cvH, g_cvH);
    cudaGetSymbolAddress((void**)&kmH, g_kmH);
    cudaGetSymbolAddress((void**)&wH, g_wH);
    cudaGetSymbolAddress((void**)&splitF, g_split);
    cudaGetSymbolAddress((void**)&bcat, g_biasCat);
    __half* wp1H = wH;               // 131072
    __half* wp2H = wH + 131072;      // 65536
    __half* wcatH = wH + 196608;     // 262144 (wo1 rows 0-255 | wd rows 256-511)
    __half* wo2H = wH + 458752;      // 65536
    __half* wuH  = wH + 524288;      // 131072
    __half* woutH = wH + 655360;     // 524288

    const size_t sBN = (size_t)CDIM * NDIM;
    const size_t sKN = (size_t)KEYD * NDIM;
    const size_t sCC = (size_t)CDIM * CDIM;
    const size_t sKC = (size_t)KEYD * CDIM;

    static cudaStream_t sCtx = nullptr;
    static cudaEvent_t evFork = nullptr, evJoinCtx = nullptr;
    if (sCtx == nullptr) {
        cudaStreamCreateWithFlags(&sCtx, cudaStreamNonBlocking);
        cudaEventCreateWithFlags(&evFork, cudaEventDisableTiming);
        cudaEventCreateWithFlags(&evJoinCtx, cudaEventDisableTiming);
    }

    cudaFuncSetAttribute(gemm_f16<false, false, false>,
                         cudaFuncAttributeMaxDynamicSharedMemorySize, SM_FF);
    cudaFuncSetAttribute(gemm_f16<false, false, true>,
                         cudaFuncAttributeMaxDynamicSharedMemorySize, SM_FF);
    cudaFuncSetAttribute(gemm_f16<false, true, false>,
                         cudaFuncAttributeMaxDynamicSharedMemorySize, SM_FT);
    cudaFuncSetAttribute(gemm_f16<true, false, false>,
                         cudaFuncAttributeMaxDynamicSharedMemorySize, SM_TF);

    // 0) weights + bias concat
    convert_weights<<<1152, 256>>>(wp1, wp2, wo1, wo2, wd, wu, wout,
                                   bo1, bd, wH, bcat);
    // 1) pwH = softmax(feat rows); featH = fp16(feat)  (high-occupancy)
    softmax_rows16k<<<BATCH * CDIM, 512>>>(feat, pwH, featH);

    // ---- fork: context chain on sCtx, q chain on default stream ----
    cudaEventRecord(evFork, 0);
    cudaStreamWaitEvent(sCtx, evFork, 0);

    // [sCtx] context partials = featH * pwH^T (split-K=4)
    gemm_f16<false, true, false><<<dim3(4, 4, BATCH * 4), 128, SM_FT, sCtx>>>(
        featH, sBN, NDIM, pwH, sBN, NDIM, nullptr, 0,
        splitF, sCC, CDIM, nullptr, 1.f, 0, 0, NDIM, 4);
    {
        size_t total = (size_t)BATCH * sCC;
        reduce_split<<<(unsigned)((total + 255) / 256), 256, 0, sCtx>>>(
            splitF, ctxH, (int)sCC, 4, total);
    }
    // [sCtx] [c1;v] = relu([wo1;wd] @ context + [bo1;bd])
    gemm_f16<false, false, false><<<dim3(4, 4, BATCH), 128, SM_FF, sCtx>>>(
        wcatH, 0, CDIM, ctxH, sCC, CDIM, nullptr, 0,
        cvH, sCC, CDIM, bcat, 1.f, 1, 1, CDIM, 1);
    // [sCtx] km = relu(wo2 @ c1 + bo2)
    gemm_f16<false, false, false><<<dim3(4, 2, BATCH), 128, SM_FF, sCtx>>>(
        wo2H, 0, KEYD, cvH, sCC, CDIM, nullptr, 0,
        kmH, sKC, CDIM, bo2, 1.f, 1, 1, KEYD, 1);
    cudaEventRecord(evJoinCtx, sCtx);

    // [s0] q chain
    gemm_f16<false, false, false><<<dim3(128, 2, BATCH), 128, SM_FF>>>(
        wp1H, 0, CDIM, featH, sBN, NDIM, nullptr, 0,
        t1H, sKN, NDIM, bp1, 1.f, 1, 1, CDIM, 1);
    gemm_f16<false, false, false><<<dim3(128, 2, BATCH), 128, SM_FF>>>(
        wp2H, 0, KEYD, t1H, sKN, NDIM, nullptr, 0,
        qH, sKN, NDIM, bp2, 1.f, 1, 1, KEYD, 1);

    // ---- join ----
    cudaStreamWaitEvent(0, evJoinCtx, 0);

    // [s0] sim = (q^T @ km) * KEY^-0.5
    gemm_f16<true, false, false><<<dim3(4, 128, BATCH), 128, SM_TF>>>(
        qH, sKN, NDIM, kmH, sKC, CDIM, nullptr, 0,
        simH, sBN, CDIM, nullptr, 0.0625f, 0, 1, KEYD, 1);
    // [s0] softmax over K=512
    softmax_k512h<<<BATCH * NDIM, 128>>>(simH);
    // [s0] attn ctx = v @ sim^T  (v = cvH rows 256-511)
    gemm_f16<false, true, false><<<dim3(128, 2, BATCH), 128, SM_FT>>>(
        cvH + 131072, sCC, CDIM, simH, sBN, CDIM, nullptr, 0,
        t1H, sKN, NDIM, nullptr, 1.f, 0, 1, CDIM, 1);
    // [s0] ctx_up = relu(wu @ attn_ctx + bu)
    gemm_f16<false, false, false><<<dim3(128, 4, BATCH), 128, SM_FF>>>(
        wuH, 0, KEYD, t1H, sKN, NDIM, nullptr, 0,
        uH, sBN, NDIM, bu, 1.f, 1, 1, KEYD, 1);
    // [s0] out = relu(wout @ concat(ctx_up, x) + bout) -> d_out (fp32)
    gemm_f16<false, false, true><<<dim3(128, 4, BATCH), 128, SM_FF>>>(
        woutH, 0, 2 * CDIM, uH, sBN, NDIM, featH, CDIM,
        outp, sBN, NDIM, bout, 1.f, 1, 0, 2 * CDIM, 1);
}

// round 16
// speedup vs baseline: 1.0699x; 1.0101x over previous
#include <cuda_runtime.h>
#include <cuda_fp16.h>
#include <cstdint>
#include <cstddef>

// ---------------------------------------------------------------------------
// OCR head on GB300 — Round 16: R15 retry with capture-legal stream fork
// (R15 failed because sCtx received work before waiting on an event recorded
// in the capturing stream). Changes vs R14 (754.2us best):
//   - convert_weights runs on sCtx concurrent with softmax16k (after fork ev)
//   - softmax512 is warp-per-row (pure shfl, no block barriers)
// GEMMs/schedule/numerics identical to R14.
// ---------------------------------------------------------------------------

#define BATCH 4
#define CDIM 512
#define NDIM 16384
#define KEYD 256

// fp16 buffers
__device__ __half g_featH[33554432];  // feat   [B,512,N]
__device__ __half g_pwH[33554432];    // softmax(feat) [B,512,N]
__device__ __half g_simH[33554432];   // sim    [B,N,512]
__device__ __half g_uH[33554432];     // ctx_up [B,512,N]
__device__ __half g_t1H[16777216];    // t1 [B,256,N]; later attn ctx
__device__ __half g_qH[16777216];     // q  [B,256,N]
__device__ __half g_ctxH[1048576];    // context [B,512,512]
__device__ __half g_cvH[1048576];     // [B, (c1:256 | v:256), 512]
__device__ __half g_kmH[524288];      // [B,256,512]
__device__ __half g_wH[1179648];      // converted weights (packed)
__device__ float g_biasCat[512];      // [bo1 ; bd]
__device__ float g_split[16777216];   // split-K partials

// ---------------------------------------------------------------------------
__device__ __forceinline__ void mma_f16(float c[4], const uint32_t a[4],
                                        const uint32_t b[2]) {
    asm volatile(
        "mma.sync.aligned.m16n8k16.row.col.f32.f16.f16.f32 "
        "{%0,%1,%2,%3}, {%4,%5,%6,%7}, {%8,%9}, {%0,%1,%2,%3};"
        : "+f"(c[0]), "+f"(c[1]), "+f"(c[2]), "+f"(c[3])
        : "r"(a[0]), "r"(a[1]), "r"(a[2]), "r"(a[3]), "r"(b[0]), "r"(b[1]));
}
__device__ __forceinline__ void cp16(uint32_t dst, const void* src) {
    asm volatile("cp.async.cg.shared.global [%0], [%1], 16;\n"
                 :: "r"(dst), "l"(src));
}
__device__ __forceinline__ void cp_commit() {
    asm volatile("cp.async.commit_group;\n" ::: "memory");
}
__device__ __forceinline__ void cp_wait0() {
    asm volatile("cp.async.wait_group 0;\n" ::: "memory");
}
__device__ __forceinline__ void cp_wait_all() {
    asm volatile("cp.async.wait_all;\n" ::: "memory");
}
__device__ __forceinline__ void ldsm_x4(uint32_t& r0, uint32_t& r1,
                                        uint32_t& r2, uint32_t& r3,
                                        uint32_t addr) {
    asm volatile("ldmatrix.sync.aligned.m8n8.x4.shared.b16 {%0,%1,%2,%3}, [%4];"
                 : "=r"(r0), "=r"(r1), "=r"(r2), "=r"(r3) : "r"(addr));
}
__device__ __forceinline__ void ldsm_x4_t(uint32_t& r0, uint32_t& r1,
                                          uint32_t& r2, uint32_t& r3,
                                          uint32_t addr) {
    asm volatile("ldmatrix.sync.aligned.m8n8.x4.trans.shared.b16 {%0,%1,%2,%3}, [%4];"
                 : "=r"(r0), "=r"(r1), "=r"(r2), "=r"(r3) : "r"(addr));
}

// ---------------------------------------------------------------------------
// fp16 batched GEMM (R9/R10 body): C[m,n]=act(alpha*sum_k opA*opB+bias[m]).
// TA: A [K,M] else [M,K]; TB: B [N,K] else [K,N]. CONCAT: B k>=ksplitB from B2.
// CTA 128x128, BK=64, 128 thr, warp tile 64x64, 2-stage cp.async + frag pipe.
// ---------------------------------------------------------------------------
template <bool TA, bool TB, bool CONCAT>
__global__ void __launch_bounds__(128, 2)
gemm_f16(const __half* __restrict__ A, size_t sA, int lda,
         const __half* __restrict__ B, size_t sB, int ldb,
         const __half* __restrict__ B2, int ksplitB,
         void* __restrict__ Cv, size_t sCz, int ldc,
         const float* __restrict__ bias, float alpha, int doRelu, int outHalf,
         int K, int nsplit) {
    constexpr int SA_ROW = 144;
    constexpr int SKM_ROW = 272;
    constexpr int ASZ = TA ? 64 * SKM_ROW : 128 * SA_ROW;
    constexpr int BSZ = TB ? 128 * SA_ROW : 64 * SKM_ROW;
    constexpr int STG = ASZ + BSZ;

    extern __shared__ __align__(16) char smem[];
    uint32_t base = (uint32_t)__cvta_generic_to_shared(smem);

    int z = blockIdx.z;
    int b = z / nsplit;
    int sidx = z - b * nsplit;
    int kchunk = K / nsplit;
    int kbeg = sidx * kchunk;
    int niter = kchunk >> 6;

    const __half* Ab = A + (size_t)b * sA;
    const __half* Bb = B + (size_t)b * sB;
    const __half* B2b = CONCAT ? (B2 + (size_t)b * sB) : (const __half*)nullptr;

    int m0 = blockIdx.y * 128;
    int n0 = blockIdx.x * 128;
    int tid = threadIdx.x;
    int warp = tid >> 5, lane = tid & 31;
    int g = lane >> 2, r = lane & 3;
    int wm = warp & 1, wn = warp >> 1;
    int warp_m0 = wm * 64, warp_n0 = wn * 64;

    int mo8 = (lane & 7) + ((lane >> 3) & 1) * 8;
    int khalf = lane >> 4;
    int kq = (lane & 7) + ((lane >> 4) & 1) * 8;
    int chalf = (lane >> 3) & 1;

    float acc[4][8][4];
    #pragma unroll
    for (int i = 0; i < 4; i++)
        #pragma unroll
        for (int j = 0; j < 8; j++)
            #pragma unroll
            for (int e = 0; e < 4; e++) acc[i][j][e] = 0.f;

    auto prefetch = [&](int st, int k0) {
        uint32_t ab = base + st * STG;
        uint32_t bb = ab + ASZ;
        if (TA) {
            #pragma unroll
            for (int p = 0; p < 8; p++) {
                int idx = tid + p * 128;
                int row = idx >> 4, mc = idx & 15;
                cp16(ab + row * SKM_ROW + mc * 16,
                     Ab + (size_t)(k0 + row) * lda + m0 + mc * 8);
            }
        } else {
            #pragma unroll
            for (int p = 0; p < 8; p++) {
                int idx = tid + p * 128;
                int row = idx >> 3, kc = idx & 7;
                cp16(ab + row * SA_ROW + kc * 16,
                     Ab + (size_t)(m0 + row) * lda + k0 + kc * 8);
            }
        }
        if (TB) {
            #pragma unroll
            for (int p = 0; p < 8; p++) {
                int idx = tid + p * 128;
                int row = idx >> 3, kc = idx & 7;
                cp16(bb + row * SA_ROW + kc * 16,
                     Bb + (size_t)(n0 + row) * ldb + k0 + kc * 8);
            }
        } else {
            #pragma unroll
            for (int p = 0; p < 8; p++) {
                int idx = tid + p * 128;
                int row = idx >> 4, nc = idx & 15;
                int kr = k0 + row;
                const __half* src;
                if (CONCAT && kr >= ksplitB)
                    src = B2b + (size_t)(kr - ksplitB) * ldb + n0 + nc * 8;
                else
                    src = Bb + (size_t)kr * ldb + n0 + nc * 8;
                cp16(bb + row * SKM_ROW + nc * 16, src);
            }
        }
        cp_commit();
    };

    prefetch(0, kbeg);

    uint32_t af[2][4][4], bf[2][8][2];

    for (int it = 0; it < niter; it++) {
        int st = it & 1;
        cp_wait0();
        __syncthreads();
        if (it + 1 < niter) prefetch(st ^ 1, kbeg + (it + 1) * 64);

        uint32_t ab = base + st * STG;
        uint32_t bb = ab + ASZ;

        auto load_frags = [&](int fb, int ks) {
            if (TA) {
                #pragma unroll
                for (int i = 0; i < 4; i++) {
                    uint32_t addr = ab + (ks * 16 + kq) * SKM_ROW +
                                    (warp_m0 + i * 16) * 2 + chalf * 16;
                    ldsm_x4_t(af[fb][i][0], af[fb][i][1],
                              af[fb][i][2], af[fb][i][3], addr);
                }
            } else {
                #pragma unroll
                for (int i = 0; i < 4; i++) {
                    uint32_t addr = ab + (warp_m0 + i * 16 + mo8) * SA_ROW +
                                    ks * 32 + khalf * 16;
                    ldsm_x4(af[fb][i][0], af[fb][i][1],
                            af[fb][i][2], af[fb][i][3], addr);
                }
            }
            if (TB) {
                #pragma unroll
                for (int jj = 0; jj < 4; jj++) {
                    uint32_t addr = bb + (warp_n0 + jj * 16 + mo8) * SA_ROW +
                                    ks * 32 + khalf * 16;
                    ldsm_x4(bf[fb][2 * jj][0], bf[fb][2 * jj + 1][0],
                            bf[fb][2 * jj][1], bf[fb][2 * jj + 1][1], addr);
                }
            } else {
                #pragma unroll
                for (int jj = 0; jj < 4; jj++) {
                    uint32_t addr = bb + (ks * 16 + kq) * SKM_ROW +
                                    (warp_n0 + jj * 16) * 2 + chalf * 16;
                    ldsm_x4_t(bf[fb][2 * jj][0], bf[fb][2 * jj + 1][0],
                              bf[fb][2 * jj][1], bf[fb][2 * jj + 1][1], addr);
                }
            }
        };

        load_frags(0, 0);
        #pragma unroll
        for (int ks = 0; ks < 4; ks++) {
            int cur = ks & 1;
            if (ks < 3) load_frags(cur ^ 1, ks + 1);
            #pragma unroll
            for (int i = 0; i < 4; i++)
                #pragma unroll
                for (int j = 0; j < 8; j++)
                    mma_f16(acc[i][j], af[cur][i], bf[cur][j]);
        }
        __syncthreads();
    }

    cp_wait_all();

    __half* Ch = (__half*)Cv + (size_t)z * sCz;
    float* Cf = (float*)Cv + (size_t)z * sCz;
    #pragma unroll
    for (int i = 0; i < 4; i++) {
        int m = m0 + warp_m0 + i * 16 + g;
        float bv0 = bias ? bias[m] : 0.f;
        float bv8 = bias ? bias[m + 8] : 0.f;
        #pragma unroll
        for (int j = 0; j < 8; j++) {
            int n = n0 + warp_n0 + j * 8 + 2 * r;
            float x0 = acc[i][j][0] * alpha + bv0;
            float x1 = acc[i][j][1] * alpha + bv0;
            float x2 = acc[i][j][2] * alpha + bv8;
            float x3 = acc[i][j][3] * alpha + bv8;
            if (doRelu) {
                x0 = fmaxf(x0, 0.f); x1 = fmaxf(x1, 0.f);
                x2 = fmaxf(x2, 0.f); x3 = fmaxf(x3, 0.f);
            }
            if (outHalf) {
                *(__half2*)&Ch[(size_t)m * ldc + n] = __floats2half2_rn(x0, x1);
                *(__half2*)&Ch[(size_t)(m + 8) * ldc + n] = __floats2half2_rn(x2, x3);
            } else {
                *(float2*)&Cf[(size_t)m * ldc + n] = make_float2(x0, x1);
                *(float2*)&Cf[(size_t)(m + 8) * ldc + n] = make_float2(x2, x3);
            }
        }
    }
}

// ---------------------------------------------------------------------------
// softmax over rows of 16384, high-occupancy (R14): fp16 smem row + 512 thr.
__global__ void __launch_bounds__(512)
softmax_rows16k(const float* __restrict__ x,
                __half* __restrict__ pwout,
                __half* __restrict__ xh) {
    __shared__ __half srow[NDIM];     // 32KB
    __shared__ float red[512];
    size_t row = blockIdx.x;
    const float* xr = x + row * (size_t)NDIM;
    __half* pwr = pwout + row * (size_t)NDIM;
    __half* xhr = xh + row * (size_t)NDIM;
    int tid = threadIdx.x;

    float m = -3.4e38f;
    for (int i = tid * 4; i < NDIM; i += 2048) {
        float4 v = *(const float4*)&xr[i];
        __half2 h01 = __floats2half2_rn(v.x, v.y);
        __half2 h23 = __floats2half2_rn(v.z, v.w);
        *(__half2*)&srow[i] = h01;
        *(__half2*)&srow[i + 2] = h23;
        *(__half2*)&xhr[i] = h01;
        *(__half2*)&xhr[i + 2] = h23;
        m = fmaxf(m, fmaxf(fmaxf(v.x, v.y), fmaxf(v.z, v.w)));
    }
    red[tid] = m;
    __syncthreads();
    for (int s = 256; s > 0; s >>= 1) {
        if (tid < s) red[tid] = fmaxf(red[tid], red[tid + s]);
        __syncthreads();
    }
    m = red[0];
    __syncthreads();

    float sum = 0.f;
    for (int i = tid * 4; i < NDIM; i += 2048) {
        float2 a = __half22float2(*(__half2*)&srow[i]);
        float2 b = __half22float2(*(__half2*)&srow[i + 2]);
        float e0 = __expf(a.x - m), e1 = __expf(a.y - m);
        float e2 = __expf(b.x - m), e3 = __expf(b.y - m);
        *(__half2*)&srow[i] = __floats2half2_rn(e0, e1);
        *(__half2*)&srow[i + 2] = __floats2half2_rn(e2, e3);
        sum += e0 + e1 + e2 + e3;
    }
    red[tid] = sum;
    __syncthreads();
    for (int s = 256; s > 0; s >>= 1) {
        if (tid < s) red[tid] += red[tid + s];
        __syncthreads();
    }
    float inv = 1.f / red[0];

    for (int i = tid * 4; i < NDIM; i += 2048) {
        float2 a = __half22float2(*(__half2*)&srow[i]);
        float2 b = __half22float2(*(__half2*)&srow[i + 2]);
        *(__half2*)&pwr[i] = __floats2half2_rn(a.x * inv, a.y * inv);
        *(__half2*)&pwr[i + 2] = __floats2half2_rn(b.x * inv, b.y * inv);
    }
}

// ---------------------------------------------------------------------------
// softmax over rows of 512 fp16 — warp-per-row (16 vals/lane, pure shfl).
// 256 threads = 8 rows/block; grid = B*N/8.
__global__ void __launch_bounds__(256)
softmax_k512w(__half* __restrict__ sim) {
    int warp = threadIdx.x >> 5, lane = threadIdx.x & 31;
    size_t row = (size_t)blockIdx.x * 8 + warp;
    __half* r = sim + row * 512;

    uint4 c0 = *(uint4*)&r[lane * 8];          // 8 halves
    uint4 c1 = *(uint4*)&r[256 + lane * 8];    // 8 halves
    float v[16];
    {
        const uint32_t* u0 = (const uint32_t*)&c0;
        const uint32_t* u1 = (const uint32_t*)&c1;
        #pragma unroll
        for (int i = 0; i < 4; i++) {
            float2 a = __half22float2(*(const __half2*)&u0[i]);
            float2 b = __half22float2(*(const __half2*)&u1[i]);
            v[2 * i] = a.x; v[2 * i + 1] = a.y;
            v[8 + 2 * i] = b.x; v[8 + 2 * i + 1] = b.y;
        }
    }
    float m = v[0];
    #pragma unroll
    for (int i = 1; i < 16; i++) m = fmaxf(m, v[i]);
    #pragma unroll
    for (int o = 16; o > 0; o >>= 1)
        m = fmaxf(m, __shfl_xor_sync(0xffffffffu, m, o));

    float s = 0.f;
    #pragma unroll
    for (int i = 0; i < 16; i++) {
        v[i] = __expf(v[i] - m);
        s += v[i];
    }
    #pragma unroll
    for (int o = 16; o > 0; o >>= 1)
        s += __shfl_xor_sync(0xffffffffu, s, o);
    float inv = 1.f / s;

    uint4 o0, o1;
    {
        uint32_t* u0 = (uint32_t*)&o0;
        uint32_t* u1 = (uint32_t*)&o1;
        #pragma unroll
        for (int i = 0; i < 4; i++) {
            *(__half2*)&u0[i] = __floats2half2_rn(v[2 * i] * inv,
                                                  v[2 * i + 1] * inv);
            *(__half2*)&u1[i] = __floats2half2_rn(v[8 + 2 * i] * inv,
                                                  v[8 + 2 * i + 1] * inv);
        }
    }
    *(uint4*)&r[lane * 8] = o0;
    *(uint4*)&r[256 + lane * 8] = o1;
}

__global__ void reduce_split(const float* __restrict__ in,
                             __half* __restrict__ out, int per, int nsplit,
                             size_t total) {
    size_t i = (size_t)blockIdx.x * blockDim.x + threadIdx.x;
    if (i >= total) return;
    size_t b = i / per;
    size_t r = i - b * per;
    const float* src = in + b * (size_t)nsplit * per + r;
    float s = 0.f;
    for (int ss = 0; ss < nsplit; ss++) s += src[(size_t)ss * per];
    out[i] = __float2half_rn(s);
}

// fp32->fp16 all weights (packed: wp1|wp2|(wo1;wd)|wo2|wu|wout) + bias concat.
__global__ void convert_weights(const float* __restrict__ wp1,
                                const float* __restrict__ wp2,
                                const float* __restrict__ wo1,
                                const float* __restrict__ wo2,
                                const float* __restrict__ wd,
                                const float* __restrict__ wu,
                                const float* __restrict__ wout,
                                const float* __restrict__ bo1,
                                const float* __restrict__ bd,
                                __half* __restrict__ out,
                                float* __restrict__ bcat) {
    int t = blockIdx.x * blockDim.x + threadIdx.x;
    if (t < 256) bcat[t] = bo1[t];
    else if (t < 512) bcat[t] = bd[t - 256];
    int i = t * 4;
    if (i >= 1179648) return;
    const float* src;
    int local;
    if (i < 131072)      { src = wp1;  local = i; }
    else if (i < 196608) { src = wp2;  local = i - 131072; }
    else if (i < 327680) { src = wo1;  local = i - 196608; }
    else if (i < 458752) { src = wd;   local = i - 327680; }
    else if (i < 524288) { src = wo2;  local = i - 458752; }
    else if (i < 655360) { src = wu;   local = i - 524288; }
    else                 { src = wout; local = i - 655360; }
    float4 v = *(const float4*)&src[local];
    *(__half2*)&out[i] = __floats2half2_rn(v.x, v.y);
    *(__half2*)&out[i + 2] = __floats2half2_rn(v.z, v.w);
}

// ---------------------------------------------------------------------------
static constexpr int SM_FF = 2 * (128 * 144 + 64 * 272);   // 71680
static constexpr int SM_FT = 2 * (128 * 144 + 128 * 144);  // 73728
static constexpr int SM_TF = 2 * (64 * 272 + 64 * 272);    // 69632

extern "C" void kernel_launch(void* const* d_in, const int* in_sizes, int n_in,
                              void* d_out, int out_size) {
    (void)in_sizes; (void)n_in; (void)out_size;
    const float* feat = (const float*)d_in[0];
    const float* wp1 = (const float*)d_in[2];
    const float* bp1 = (const float*)d_in[3];
    const float* wp2 = (const float*)d_in[4];
    const float* bp2 = (const float*)d_in[5];
    const float* wo1 = (const float*)d_in[6];
    const float* bo1 = (const float*)d_in[7];
    const float* wo2 = (const float*)d_in[8];
    const float* bo2 = (const float*)d_in[9];
    const float* wd  = (const float*)d_in[10];
    const float* bd  = (const float*)d_in[11];
    const float* wu  = (const float*)d_in[12];
    const float* bu  = (const float*)d_in[13];
    const float* wout = (const float*)d_in[14];
    const float* bout = (const float*)d_in[15];
    float* outp = (float*)d_out;

    __half *featH, *pwH, *simH, *uH, *t1H, *qH, *ctxH, *cvH, *kmH, *wH;
    float *splitF, *bcat;
    cudaGetSymbolAddress((void**)&featH, g_featH);
    cudaGetSymbolAddress((void**)&pwH, g_pwH);
    cudaGetSymbolAddress((void**)&simH, g_simH);
    cudaGetSymbolAddress((void**)&uH, g_uH);
    cudaGetSymbolAddress((void**)&t1H, g_t1H);
    cudaGetSymbolAddress((void**)&qH, g_qH);
    cudaGetSymbolAddress((void**)&ctxH, g_ctxH);
    cudaGetSymbolAddress((void**)&cvH, g_cvH);
    cudaGetSymbolAddress((void**)&kmH, g_kmH);
    cudaGetSymbolAddress((void**)&wH, g_wH);
    cudaGetSymbolAddress((void**)&splitF, g_split);
    cudaGetSymbolAddress((void**)&bcat, g_biasCat);
    __half* wp1H = wH;               // 131072
    __half* wp2H = wH + 131072;      // 65536
    __half* wcatH = wH + 196608;     // 262144 (wo1 rows 0-255 | wd rows 256-511)
    __half* wo2H = wH + 458752;      // 65536
    __half* wuH  = wH + 524288;      // 131072
    __half* woutH = wH + 655360;     // 524288

    const size_t sBN = (size_t)CDIM * NDIM;
    const size_t sKN = (size_t)KEYD * NDIM;
    const size_t sCC = (size_t)CDIM * CDIM;
    const size_t sKC = (size_t)KEYD * CDIM;

    static cudaStream_t sCtx = nullptr;
    static cudaEvent_t evFork = nullptr, evSm = nullptr, evW = nullptr;
    static cudaEvent_t evJoinCtx = nullptr;
    if (sCtx == nullptr) {
        cudaStreamCreateWithFlags(&sCtx, cudaStreamNonBlocking);
        cudaEventCreateWithFlags(&evFork, cudaEventDisableTiming);
        cudaEventCreateWithFlags(&evSm, cudaEventDisableTiming);
        cudaEventCreateWithFlags(&evW, cudaEventDisableTiming);
        cudaEventCreateWithFlags(&evJoinCtx, cudaEventDisableTiming);
    }

    cudaFuncSetAttribute(gemm_f16<false, false, false>,
                         cudaFuncAttributeMaxDynamicSharedMemorySize, SM_FF);
    cudaFuncSetAttribute(gemm_f16<false, false, true>,
                         cudaFuncAttributeMaxDynamicSharedMemorySize, SM_FF);
    cudaFuncSetAttribute(gemm_f16<false, true, false>,
                         cudaFuncAttributeMaxDynamicSharedMemorySize, SM_FT);
    cudaFuncSetAttribute(gemm_f16<true, false, false>,
                         cudaFuncAttributeMaxDynamicSharedMemorySize, SM_TF);

    // ---- capture-legal fork: event recorded on the capturing stream FIRST ----
    cudaEventRecord(evFork, 0);
    cudaStreamWaitEvent(sCtx, evFork, 0);

    // [sCtx] weights + bias concat (concurrent with softmax16k on s0)
    convert_weights<<<1152, 256, 0, sCtx>>>(wp1, wp2, wo1, wo2, wd, wu, wout,
                                            bo1, bd, wH, bcat);
    cudaEventRecord(evW, sCtx);

    // [s0] pwH = softmax(feat rows); featH = fp16(feat)
    softmax_rows16k<<<BATCH * CDIM, 512>>>(feat, pwH, featH);
    cudaEventRecord(evSm, 0);

    // cross-dependencies: ctx chain (sCtx) needs softmax; q chain (s0) needs W
    cudaStreamWaitEvent(sCtx, evSm, 0);
    cudaStreamWaitEvent(0, evW, 0);

    // [sCtx] context partials = featH * pwH^T (split-K=4)
    gemm_f16<false, true, false><<<dim3(4, 4, BATCH * 4), 128, SM_FT, sCtx>>>(
        featH, sBN, NDIM, pwH, sBN, NDIM, nullptr, 0,
        splitF, sCC, CDIM, nullptr, 1.f, 0, 0, NDIM, 4);
    {
        size_t total = (size_t)BATCH * sCC;
        reduce_split<<<(unsigned)((total + 255) / 256), 256, 0, sCtx>>>(
            splitF, ctxH, (int)sCC, 4, total);
    }
    // [sCtx] [c1;v] = relu([wo1;wd] @ context + [bo1;bd])
    gemm_f16<false, false, false><<<dim3(4, 4, BATCH), 128, SM_FF, sCtx>>>(
        wcatH, 0, CDIM, ctxH, sCC, CDIM, nullptr, 0,
        cvH, sCC, CDIM, bcat, 1.f, 1, 1, CDIM, 1);
    // [sCtx] km = relu(wo2 @ c1 + bo2)
    gemm_f16<false, false, false><<<dim3(4, 2, BATCH), 128, SM_FF, sCtx>>>(
        wo2H, 0, KEYD, cvH, sCC, CDIM, nullptr, 0,
        kmH, sKC, CDIM, bo2, 1.f, 1, 1, KEYD, 1);
    cudaEventRecord(evJoinCtx, sCtx);

    // [s0] q chain
    gemm_f16<false, false, false><<<dim3(128, 2, BATCH), 128, SM_FF>>>(
        wp1H, 0, CDIM, featH, sBN, NDIM, nullptr, 0,
        t1H, sKN, NDIM, bp1, 1.f, 1, 1, CDIM, 1);
    gemm_f16<false, false, false><<<dim3(128, 2, BATCH), 128, SM_FF>>>(
        wp2H, 0, KEYD, t1H, sKN, NDIM, nullptr, 0,
        qH, sKN, NDIM, bp2, 1.f, 1, 1, KEYD, 1);

    // ---- join ----
    cudaStreamWaitEvent(0, evJoinCtx, 0);

    // [s0] sim = (q^T @ km) * KEY^-0.5
    gemm_f16<true, false, false><<<dim3(4, 128, BATCH), 128, SM_TF>>>(
        qH, sKN, NDIM, kmH, sKC, CDIM, nullptr, 0,
        simH, sBN, CDIM, nullptr, 0.0625f, 0, 1, KEYD, 1);
    // [s0] softmax over K=512 (warp-per-row)
    softmax_k512w<<<BATCH * NDIM / 8, 256>>>(simH);
    // [s0] attn ctx = v @ sim^T  (v = cvH rows 256-511)
    gemm_f16<false, true, false><<<dim3(128, 2, BATCH), 128, SM_FT>>>(
        cvH + 131072, sCC, CDIM, simH, sBN, CDIM, nullptr, 0,
        t1H, sKN, NDIM, nullptr, 1.f, 0, 1, CDIM, 1);
    // [s0] ctx_up = relu(wu @ attn_ctx + bu)
    gemm_f16<false, false, false><<<dim3(128, 4, BATCH), 128, SM_FF>>>(
        wuH, 0, KEYD, t1H, sKN, NDIM, nullptr, 0,
        uH, sBN, NDIM, bu, 1.f, 1, 1, KEYD, 1);
    // [s0] out = relu(wout @ concat(ctx_up, x) + bout) -> d_out (fp32)
    gemm_f16<false, false, true><<<dim3(128, 4, BATCH), 128, SM_FF>>>(
        woutH, 0, 2 * CDIM, uH, sBN, NDIM, featH, CDIM,
        outp, sBN, NDIM, bout, 1.f, 1, 0, 2 * CDIM, 1);
}

// round 17
// speedup vs baseline: 1.0727x; 1.0027x over previous
#include <cuda_runtime.h>
#include <cuda_fp16.h>
#include <cstdint>
#include <cstddef>

// ---------------------------------------------------------------------------
// OCR head on GB300 — Round 17: R16 config (best, 746.7us) with context
// split-K partials stored fp16 (halves reduce_split traffic on the ctx-chain
// critical path). Everything else identical: fp16 mma.sync GEMMs at the
// measured HMMA ceiling, high-occupancy softmax16k, warp-per-row softmax512,
// capture-legal two-stream fork.
// ---------------------------------------------------------------------------

#define BATCH 4
#define CDIM 512
#define NDIM 16384
#define KEYD 256

// fp16 buffers
__device__ __half g_featH[33554432];  // feat   [B,512,N]
__device__ __half g_pwH[33554432];    // softmax(feat) [B,512,N]
__device__ __half g_simH[33554432];   // sim    [B,N,512]
__device__ __half g_uH[33554432];     // ctx_up [B,512,N]
__device__ __half g_t1H[16777216];    // t1 [B,256,N]; later attn ctx
__device__ __half g_qH[16777216];     // q  [B,256,N]
__device__ __half g_ctxH[1048576];    // context [B,512,512]
__device__ __half g_cvH[1048576];     // [B, (c1:256 | v:256), 512]
__device__ __half g_kmH[524288];      // [B,256,512]
__device__ __half g_wH[1179648];      // converted weights (packed)
__device__ float g_biasCat[512];      // [bo1 ; bd]
__device__ __half g_splitH[4194304];  // fp16 split-K partials [B*4,512,512]

// ---------------------------------------------------------------------------
__device__ __forceinline__ void mma_f16(float c[4], const uint32_t a[4],
                                        const uint32_t b[2]) {
    asm volatile(
        "mma.sync.aligned.m16n8k16.row.col.f32.f16.f16.f32 "
        "{%0,%1,%2,%3}, {%4,%5,%6,%7}, {%8,%9}, {%0,%1,%2,%3};"
        : "+f"(c[0]), "+f"(c[1]), "+f"(c[2]), "+f"(c[3])
        : "r"(a[0]), "r"(a[1]), "r"(a[2]), "r"(a[3]), "r"(b[0]), "r"(b[1]));
}
__device__ __forceinline__ void cp16(uint32_t dst, const void* src) {
    asm volatile("cp.async.cg.shared.global [%0], [%1], 16;\n"
                 :: "r"(dst), "l"(src));
}
__device__ __forceinline__ void cp_commit() {
    asm volatile("cp.async.commit_group;\n" ::: "memory");
}
__device__ __forceinline__ void cp_wait0() {
    asm volatile("cp.async.wait_group 0;\n" ::: "memory");
}
__device__ __forceinline__ void cp_wait_all() {
    asm volatile("cp.async.wait_all;\n" ::: "memory");
}
__device__ __forceinline__ void ldsm_x4(uint32_t& r0, uint32_t& r1,
                                        uint32_t& r2, uint32_t& r3,
                                        uint32_t addr) {
    asm volatile("ldmatrix.sync.aligned.m8n8.x4.shared.b16 {%0,%1,%2,%3}, [%4];"
                 : "=r"(r0), "=r"(r1), "=r"(r2), "=r"(r3) : "r"(addr));
}
__device__ __forceinline__ void ldsm_x4_t(uint32_t& r0, uint32_t& r1,
                                          uint32_t& r2, uint32_t& r3,
                                          uint32_t addr) {
    asm volatile("ldmatrix.sync.aligned.m8n8.x4.trans.shared.b16 {%0,%1,%2,%3}, [%4];"
                 : "=r"(r0), "=r"(r1), "=r"(r2), "=r"(r3) : "r"(addr));
}

// ---------------------------------------------------------------------------
// fp16 batched GEMM (R9/R10 body): C[m,n]=act(alpha*sum_k opA*opB+bias[m]).
// TA: A [K,M] else [M,K]; TB: B [N,K] else [K,N]. CONCAT: B k>=ksplitB from B2.
// CTA 128x128, BK=64, 128 thr, warp tile 64x64, 2-stage cp.async + frag pipe.
// ---------------------------------------------------------------------------
template <bool TA, bool TB, bool CONCAT>
__global__ void __launch_bounds__(128, 2)
gemm_f16(const __half* __restrict__ A, size_t sA, int lda,
         const __half* __restrict__ B, size_t sB, int ldb,
         const __half* __restrict__ B2, int ksplitB,
         void* __restrict__ Cv, size_t sCz, int ldc,
         const float* __restrict__ bias, float alpha, int doRelu, int outHalf,
         int K, int nsplit) {
    constexpr int SA_ROW = 144;
    constexpr int SKM_ROW = 272;
    constexpr int ASZ = TA ? 64 * SKM_ROW : 128 * SA_ROW;
    constexpr int BSZ = TB ? 128 * SA_ROW : 64 * SKM_ROW;
    constexpr int STG = ASZ + BSZ;

    extern __shared__ __align__(16) char smem[];
    uint32_t base = (uint32_t)__cvta_generic_to_shared(smem);

    int z = blockIdx.z;
    int b = z / nsplit;
    int sidx = z - b * nsplit;
    int kchunk = K / nsplit;
    int kbeg = sidx * kchunk;
    int niter = kchunk >> 6;

    const __half* Ab = A + (size_t)b * sA;
    const __half* Bb = B + (size_t)b * sB;
    const __half* B2b = CONCAT ? (B2 + (size_t)b * sB) : (const __half*)nullptr;

    int m0 = blockIdx.y * 128;
    int n0 = blockIdx.x * 128;
    int tid = threadIdx.x;
    int warp = tid >> 5, lane = tid & 31;
    int g = lane >> 2, r = lane & 3;
    int wm = warp & 1, wn = warp >> 1;
    int warp_m0 = wm * 64, warp_n0 = wn * 64;

    int mo8 = (lane & 7) + ((lane >> 3) & 1) * 8;
    int khalf = lane >> 4;
    int kq = (lane & 7) + ((lane >> 4) & 1) * 8;
    int chalf = (lane >> 3) & 1;

    float acc[4][8][4];
    #pragma unroll
    for (int i = 0; i < 4; i++)
        #pragma unroll
        for (int j = 0; j < 8; j++)
            #pragma unroll
            for (int e = 0; e < 4; e++) acc[i][j][e] = 0.f;

    auto prefetch = [&](int st, int k0) {
        uint32_t ab = base + st * STG;
        uint32_t bb = ab + ASZ;
        if (TA) {
            #pragma unroll
            for (int p = 0; p < 8; p++) {
                int idx = tid + p * 128;
                int row = idx >> 4, mc = idx & 15;
                cp16(ab + row * SKM_ROW + mc * 16,
                     Ab + (size_t)(k0 + row) * lda + m0 + mc * 8);
            }
        } else {
            #pragma unroll
            for (int p = 0; p < 8; p++) {
                int idx = tid + p * 128;
                int row = idx >> 3, kc = idx & 7;
                cp16(ab + row * SA_ROW + kc * 16,
                     Ab + (size_t)(m0 + row) * lda + k0 + kc * 8);
            }
        }
        if (TB) {
            #pragma unroll
            for (int p = 0; p < 8; p++) {
                int idx = tid + p * 128;
                int row = idx >> 3, kc = idx & 7;
                cp16(bb + row * SA_ROW + kc * 16,
                     Bb + (size_t)(n0 + row) * ldb + k0 + kc * 8);
            }
        } else {
            #pragma unroll
            for (int p = 0; p < 8; p++) {
                int idx = tid + p * 128;
                int row = idx >> 4, nc = idx & 15;
                int kr = k0 + row;
                const __half* src;
                if (CONCAT && kr >= ksplitB)
                    src = B2b + (size_t)(kr - ksplitB) * ldb + n0 + nc * 8;
                else
                    src = Bb + (size_t)kr * ldb + n0 + nc * 8;
                cp16(bb + row * SKM_ROW + nc * 16, src);
            }
        }
        cp_commit();
    };

    prefetch(0, kbeg);

    uint32_t af[2][4][4], bf[2][8][2];

    for (int it = 0; it < niter; it++) {
        int st = it & 1;
        cp_wait0();
        __syncthreads();
        if (it + 1 < niter) prefetch(st ^ 1, kbeg + (it + 1) * 64);

        uint32_t ab = base + st * STG;
        uint32_t bb = ab + ASZ;

        auto load_frags = [&](int fb, int ks) {
            if (TA) {
                #pragma unroll
                for (int i = 0; i < 4; i++) {
                    uint32_t addr = ab + (ks * 16 + kq) * SKM_ROW +
                                    (warp_m0 + i * 16) * 2 + chalf * 16;
                    ldsm_x4_t(af[fb][i][0], af[fb][i][1],
                              af[fb][i][2], af[fb][i][3], addr);
                }
            } else {
                #pragma unroll
                for (int i = 0; i < 4; i++) {
                    uint32_t addr = ab + (warp_m0 + i * 16 + mo8) * SA_ROW +
                                    ks * 32 + khalf * 16;
                    ldsm_x4(af[fb][i][0], af[fb][i][1],
                            af[fb][i][2], af[fb][i][3], addr);
                }
            }
            if (TB) {
                #pragma unroll
                for (int jj = 0; jj < 4; jj++) {
                    uint32_t addr = bb + (warp_n0 + jj * 16 + mo8) * SA_ROW +
                                    ks * 32 + khalf * 16;
                    ldsm_x4(bf[fb][2 * jj][0], bf[fb][2 * jj + 1][0],
                            bf[fb][2 * jj][1], bf[fb][2 * jj + 1][1], addr);
                }
            } else {
                #pragma unroll
                for (int jj = 0; jj < 4; jj++) {
                    uint32_t addr = bb + (ks * 16 + kq) * SKM_ROW +
                                    (warp_n0 + jj * 16) * 2 + chalf * 16;
                    ldsm_x4_t(bf[fb][2 * jj][0], bf[fb][2 * jj + 1][0],
                              bf[fb][2 * jj][1], bf[fb][2 * jj + 1][1], addr);
                }
            }
        };

        load_frags(0, 0);
        #pragma unroll
        for (int ks = 0; ks < 4; ks++) {
            int cur = ks & 1;
            if (ks < 3) load_frags(cur ^ 1, ks + 1);
            #pragma unroll
            for (int i = 0; i < 4; i++)
                #pragma unroll
                for (int j = 0; j < 8; j++)
                    mma_f16(acc[i][j], af[cur][i], bf[cur][j]);
        }
        __syncthreads();
    }

    cp_wait_all();

    __half* Ch = (__half*)Cv + (size_t)z * sCz;
    float* Cf = (float*)Cv + (size_t)z * sCz;
    #pragma unroll
    for (int i = 0; i < 4; i++) {
        int m = m0 + warp_m0 + i * 16 + g;
        float bv0 = bias ? bias[m] : 0.f;
        float bv8 = bias ? bias[m + 8] : 0.f;
        #pragma unroll
        for (int j = 0; j < 8; j++) {
            int n = n0 + warp_n0 + j * 8 + 2 * r;
            float x0 = acc[i][j][0] * alpha + bv0;
            float x1 = acc[i][j][1] * alpha + bv0;
            float x2 = acc[i][j][2] * alpha + bv8;
            float x3 = acc[i][j][3] * alpha + bv8;
            if (doRelu) {
                x0 = fmaxf(x0, 0.f); x1 = fmaxf(x1, 0.f);
                x2 = fmaxf(x2, 0.f); x3 = fmaxf(x3, 0.f);
            }
            if (outHalf) {
                *(__half2*)&Ch[(size_t)m * ldc + n] = __floats2half2_rn(x0, x1);
                *(__half2*)&Ch[(size_t)(m + 8) * ldc + n] = __floats2half2_rn(x2, x3);
            } else {
                *(float2*)&Cf[(size_t)m * ldc + n] = make_float2(x0, x1);
                *(float2*)&Cf[(size_t)(m + 8) * ldc + n] = make_float2(x2, x3);
            }
        }
    }
}

// ---------------------------------------------------------------------------
// softmax over rows of 16384, high-occupancy: fp16 smem row + 512 threads.
__global__ void __launch_bounds__(512)
softmax_rows16k(const float* __restrict__ x,
                __half* __restrict__ pwout,
                __half* __restrict__ xh) {
    __shared__ __half srow[NDIM];     // 32KB
    __shared__ float red[512];
    size_t row = blockIdx.x;
    const float* xr = x + row * (size_t)NDIM;
    __half* pwr = pwout + row * (size_t)NDIM;
    __half* xhr = xh + row * (size_t)NDIM;
    int tid = threadIdx.x;

    float m = -3.4e38f;
    for (int i = tid * 4; i < NDIM; i += 2048) {
        float4 v = *(const float4*)&xr[i];
        __half2 h01 = __floats2half2_rn(v.x, v.y);
        __half2 h23 = __floats2half2_rn(v.z, v.w);
        *(__half2*)&srow[i] = h01;
        *(__half2*)&srow[i + 2] = h23;
        *(__half2*)&xhr[i] = h01;
        *(__half2*)&xhr[i + 2] = h23;
        m = fmaxf(m, fmaxf(fmaxf(v.x, v.y), fmaxf(v.z, v.w)));
    }
    red[tid] = m;
    __syncthreads();
    for (int s = 256; s > 0; s >>= 1) {
        if (tid < s) red[tid] = fmaxf(red[tid], red[tid + s]);
        __syncthreads();
    }
    m = red[0];
    __syncthreads();

    float sum = 0.f;
    for (int i = tid * 4; i < NDIM; i += 2048) {
        float2 a = __half22float2(*(__half2*)&srow[i]);
        float2 b = __half22float2(*(__half2*)&srow[i + 2]);
        float e0 = __expf(a.x - m), e1 = __expf(a.y - m);
        float e2 = __expf(b.x - m), e3 = __expf(b.y - m);
        *(__half2*)&srow[i] = __floats2half2_rn(e0, e1);
        *(__half2*)&srow[i + 2] = __floats2half2_rn(e2, e3);
        sum += e0 + e1 + e2 + e3;
    }
    red[tid] = sum;
    __syncthreads();
    for (int s = 256; s > 0; s >>= 1) {
        if (tid < s) red[tid] += red[tid + s];
        __syncthreads();
    }
    float inv = 1.f / red[0];

    for (int i = tid * 4; i < NDIM; i += 2048) {
        float2 a = __half22float2(*(__half2*)&srow[i]);
        float2 b = __half22float2(*(__half2*)&srow[i + 2]);
        *(__half2*)&pwr[i] = __floats2half2_rn(a.x * inv, a.y * inv);
        *(__half2*)&pwr[i + 2] = __floats2half2_rn(b.x * inv, b.y * inv);
    }
}

// ---------------------------------------------------------------------------
// softmax over rows of 512 fp16 — warp-per-row (16 vals/lane, pure shfl).
__global__ void __launch_bounds__(256)
softmax_k512w(__half* __restrict__ sim) {
    int warp = threadIdx.x >> 5, lane = threadIdx.x & 31;
    size_t row = (size_t)blockIdx.x * 8 + warp;
    __half* r = sim + row * 512;

    uint4 c0 = *(uint4*)&r[lane * 8];
    uint4 c1 = *(uint4*)&r[256 + lane * 8];
    float v[16];
    {
        const uint32_t* u0 = (const uint32_t*)&c0;
        const uint32_t* u1 = (const uint32_t*)&c1;
        #pragma unroll
        for (int i = 0; i < 4; i++) {
            float2 a = __half22float2(*(const __half2*)&u0[i]);
            float2 b = __half22float2(*(const __half2*)&u1[i]);
            v[2 * i] = a.x; v[2 * i + 1] = a.y;
            v[8 + 2 * i] = b.x; v[8 + 2 * i + 1] = b.y;
        }
    }
    float m = v[0];
    #pragma unroll
    for (int i = 1; i < 16; i++) m = fmaxf(m, v[i]);
    #pragma unroll
    for (int o = 16; o > 0; o >>= 1)
        m = fmaxf(m, __shfl_xor_sync(0xffffffffu, m, o));

    float s = 0.f;
    #pragma unroll
    for (int i = 0; i < 16; i++) {
        v[i] = __expf(v[i] - m);
        s += v[i];
    }
    #pragma unroll
    for (int o = 16; o > 0; o >>= 1)
        s += __shfl_xor_sync(0xffffffffu, s, o);
    float inv = 1.f / s;

    uint4 o0, o1;
    {
        uint32_t* u0 = (uint32_t*)&o0;
        uint32_t* u1 = (uint32_t*)&o1;
        #pragma unroll
        for (int i = 0; i < 4; i++) {
            *(__half2*)&u0[i] = __floats2half2_rn(v[2 * i] * inv,
                                                  v[2 * i + 1] * inv);
            *(__half2*)&u1[i] = __floats2half2_rn(v[8 + 2 * i] * inv,
                                                  v[8 + 2 * i + 1] * inv);
        }
    }
    *(uint4*)&r[lane * 8] = o0;
    *(uint4*)&r[256 + lane * 8] = o1;
}

// Sum fp16 split-K partials -> fp16 (fp32 accumulate)
__global__ void reduce_split_h(const __half* __restrict__ in,
                               __half* __restrict__ out, int per, int nsplit,
                               size_t total) {
    size_t i = ((size_t)blockIdx.x * blockDim.x + threadIdx.x) * 2;
    if (i >= total) return;
    size_t b = i / per;
    size_t r = i - b * per;
    const __half* src = in + b * (size_t)nsplit * per + r;
    float s0 = 0.f, s1 = 0.f;
    for (int ss = 0; ss < nsplit; ss++) {
        float2 p = __half22float2(*(const __half2*)&src[(size_t)ss * per]);
        s0 += p.x; s1 += p.y;
    }
    *(__half2*)&out[i] = __floats2half2_rn(s0, s1);
}

// fp32->fp16 all weights (packed: wp1|wp2|(wo1;wd)|wo2|wu|wout) + bias concat.
__global__ void convert_weights(const float* __restrict__ wp1,
                                const float* __restrict__ wp2,
                                const float* __restrict__ wo1,
                                const float* __restrict__ wo2,
                                const float* __restrict__ wd,
                                const float* __restrict__ wu,
                                const float* __restrict__ wout,
                                const float* __restrict__ bo1,
                                const float* __restrict__ bd,
                                __half* __restrict__ out,
                                float* __restrict__ bcat) {
    int t = blockIdx.x * blockDim.x + threadIdx.x;
    if (t < 256) bcat[t] = bo1[t];
    else if (t < 512) bcat[t] = bd[t - 256];
    int i = t * 4;
    if (i >= 1179648) return;
    const float* src;
    int local;
    if (i < 131072)      { src = wp1;  local = i; }
    else if (i < 196608) { src = wp2;  local = i - 131072; }
    else if (i < 327680) { src = wo1;  local = i - 196608; }
    else if (i < 458752) { src = wd;   local = i - 327680; }
    else if (i < 524288) { src = wo2;  local = i - 458752; }
    else if (i < 655360) { src = wu;   local = i - 524288; }
    else                 { src = wout; local = i - 655360; }
    float4 v = *(const float4*)&src[local];
    *(__half2*)&out[i] = __floats2half2_rn(v.x, v.y);
    *(__half2*)&out[i + 2] = __floats2half2_rn(v.z, v.w);
}

// ---------------------------------------------------------------------------
static constexpr int SM_FF = 2 * (128 * 144 + 64 * 272);   // 71680
static constexpr int SM_FT = 2 * (128 * 144 + 128 * 144);  // 73728
static constexpr int SM_TF = 2 * (64 * 272 + 64 * 272);    // 69632

extern "C" void kernel_launch(void* const* d_in, const int* in_sizes, int n_in,
                              void* d_out, int out_size) {
    (void)in_sizes; (void)n_in; (void)out_size;
    const float* feat = (const float*)d_in[0];
    const float* wp1 = (const float*)d_in[2];
    const float* bp1 = (const float*)d_in[3];
    const float* wp2 = (const float*)d_in[4];
    const float* bp2 = (const float*)d_in[5];
    const float* wo1 = (const float*)d_in[6];
    const float* bo1 = (const float*)d_in[7];
    const float* wo2 = (const float*)d_in[8];
    const float* bo2 = (const float*)d_in[9];
    const float* wd  = (const float*)d_in[10];
    const float* bd  = (const float*)d_in[11];
    const float* wu  = (const float*)d_in[12];
    const float* bu  = (const float*)d_in[13];
    const float* wout = (const float*)d_in[14];
    const float* bout = (const float*)d_in[15];
    float* outp = (float*)d_out;

    __half *featH, *pwH, *simH, *uH, *t1H, *qH, *ctxH, *cvH, *kmH, *wH, *splitH;
    float* bcat;
    cudaGetSymbolAddress((void**)&featH, g_featH);
    cudaGetSymbolAddress((void**)&pwH, g_pwH);
    cudaGetSymbolAddress((void**)&simH, g_simH);
    cudaGetSymbolAddress((void**)&uH, g_uH);
    cudaGetSymbolAddress((void**)&t1H, g_t1H);
    cudaGetSymbolAddress((void**)&qH, g_qH);
    cudaGetSymbolAddress((void**)&ctxH, g_ctxH);
    cudaGetSymbolAddress((void**)&cvH, g_cvH);
    cudaGetSymbolAddress((void**)&kmH, g_kmH);
    cudaGetSymbolAddress((void**)&wH, g_wH);
    cudaGetSymbolAddress((void**)&splitH, g_splitH);
    cudaGetSymbolAddress((void**)&bcat, g_biasCat);
    __half* wp1H = wH;               // 131072
    __half* wp2H = wH + 131072;      // 65536
    __half* wcatH = wH + 196608;     // 262144 (wo1 rows 0-255 | wd rows 256-511)
    __half* wo2H = wH + 458752;      // 65536
    __half* wuH  = wH + 524288;      // 131072
    __half* woutH = wH + 655360;     // 524288

    const size_t sBN = (size_t)CDIM * NDIM;
    const size_t sKN = (size_t)KEYD * NDIM;
    const size_t sCC = (size_t)CDIM * CDIM;
    const size_t sKC = (size_t)KEYD * CDIM;

    static cudaStream_t sCtx = nullptr;
    static cudaEvent_t evFork = nullptr, evSm = nullptr, evW = nullptr;
    static cudaEvent_t evJoinCtx = nullptr;
    if (sCtx == nullptr) {
        cudaStreamCreateWithFlags(&sCtx, cudaStreamNonBlocking);
        cudaEventCreateWithFlags(&evFork, cudaEventDisableTiming);
        cudaEventCreateWithFlags(&evSm, cudaEventDisableTiming);
        cudaEventCreateWithFlags(&evW, cudaEventDisableTiming);
        cudaEventCreateWithFlags(&evJoinCtx, cudaEventDisableTiming);
    }

    cudaFuncSetAttribute(gemm_f16<false, false, false>,
                         cudaFuncAttributeMaxDynamicSharedMemorySize, SM_FF);
    cudaFuncSetAttribute(gemm_f16<false, false, true>,
                         cudaFuncAttributeMaxDynamicSharedMemorySize, SM_FF);
    cudaFuncSetAttribute(gemm_f16<false, true, false>,
                         cudaFuncAttributeMaxDynamicSharedMemorySize, SM_FT);
    cudaFuncSetAttribute(gemm_f16<true, false, false>,
                         cudaFuncAttributeMaxDynamicSharedMemorySize, SM_TF);

    // ---- capture-legal fork: event recorded on the capturing stream FIRST ----
    cudaEventRecord(evFork, 0);
    cudaStreamWaitEvent(sCtx, evFork, 0);

    // [sCtx] weights + bias concat (concurrent with softmax16k on s0)
    convert_weights<<<1152, 256, 0, sCtx>>>(wp1, wp2, wo1, wo2, wd, wu, wout,
                                            bo1, bd, wH, bcat);
    cudaEventRecord(evW, sCtx);

    // [s0] pwH = softmax(feat rows); featH = fp16(feat)
    softmax_rows16k<<<BATCH * CDIM, 512>>>(feat, pwH, featH);
    cudaEventRecord(evSm, 0);

    // cross-dependencies: ctx chain (sCtx) needs softmax; q chain (s0) needs W
    cudaStreamWaitEvent(sCtx, evSm, 0);
    cudaStreamWaitEvent(0, evW, 0);

    // [sCtx] context partials = featH * pwH^T (split-K=4, fp16 partials)
    gemm_f16<false, true, false><<<dim3(4, 4, BATCH * 4), 128, SM_FT, sCtx>>>(
        featH, sBN, NDIM, pwH, sBN, NDIM, nullptr, 0,
        splitH, sCC, CDIM, nullptr, 1.f, 0, 1, NDIM, 4);
    {
        size_t total = (size_t)BATCH * sCC;
        reduce_split_h<<<(unsigned)((total / 2 + 255) / 256), 256, 0, sCtx>>>(
            splitH, ctxH, (int)sCC, 4, total);
    }
    // [sCtx] [c1;v] = relu([wo1;wd] @ context + [bo1;bd])
    gemm_f16<false, false, false><<<dim3(4, 4, BATCH), 128, SM_FF, sCtx>>>(
        wcatH, 0, CDIM, ctxH, sCC, CDIM, nullptr, 0,
        cvH, sCC, CDIM, bcat, 1.f, 1, 1, CDIM, 1);
    // [sCtx] km = relu(wo2 @ c1 + bo2)
    gemm_f16<false, false, false><<<dim3(4, 2, BATCH), 128, SM_FF, sCtx>>>(
        wo2H, 0, KEYD, cvH, sCC, CDIM, nullptr, 0,
        kmH, sKC, CDIM, bo2, 1.f, 1, 1, KEYD, 1);
    cudaEventRecord(evJoinCtx, sCtx);

    // [s0] q chain
    gemm_f16<false, false, false><<<dim3(128, 2, BATCH), 128, SM_FF>>>(
        wp1H, 0, CDIM, featH, sBN, NDIM, nullptr, 0,
        t1H, sKN, NDIM, bp1, 1.f, 1, 1, CDIM, 1);
    gemm_f16<false, false, false><<<dim3(128, 2, BATCH), 128, SM_FF>>>(
        wp2H, 0, KEYD, t1H, sKN, NDIM, nullptr, 0,
        qH, sKN, NDIM, bp2, 1.f, 1, 1, KEYD, 1);

    // ---- join ----
    cudaStreamWaitEvent(0, evJoinCtx, 0);

    // [s0] sim = (q^T @ km) * KEY^-0.5
    gemm_f16<true, false, false><<<dim3(4, 128, BATCH), 128, SM_TF>>>(
        qH, sKN, NDIM, kmH, sKC, CDIM, nullptr, 0,
        simH, sBN, CDIM, nullptr, 0.0625f, 0, 1, KEYD, 1);
    // [s0] softmax over K=512 (warp-per-row)
    softmax_k512w<<<BATCH * NDIM / 8, 256>>>(simH);
    // [s0] attn ctx = v @ sim^T  (v = cvH rows 256-511)
    gemm_f16<false, true, false><<<dim3(128, 2, BATCH), 128, SM_FT>>>(
        cvH + 131072, sCC, CDIM, simH, sBN, CDIM, nullptr, 0,
        t1H, sKN, NDIM, nullptr, 1.f, 0, 1, CDIM, 1);
    // [s0] ctx_up = relu(wu @ attn_ctx + bu)
    gemm_f16<false, false, false><<<dim3(128, 4, BATCH), 128, SM_FF>>>(
        wuH, 0, KEYD, t1H, sKN, NDIM, nullptr, 0,
        uH, sBN, NDIM, bu, 1.f, 1, 1, KEYD, 1);
    // [s0] out = relu(wout @ concat(ctx_up, x) + bout) -> d_out (fp32)
    gemm_f16<false, false, true><<<dim3(128, 4, BATCH), 128, SM_FF>>>(
        woutH, 0, 2 * CDIM, uH, sBN, NDIM, featH, CDIM,
        outp, sBN, NDIM, bout, 1.f, 1, 0, 2 * CDIM, 1);
}